// round 1
// baseline (speedup 1.0000x reference)
#include <cuda_runtime.h>
#include <math.h>
#include <float.h>

#define NN   8192
#define FIN  256
#define HIDD 256
#define NE   131072
#define KT   17
#define NCLS 10
#define NSEL 4096
#define EPSF 1e-8f

// ---------------- scratch (static device allocations; no runtime alloc) ---------
__device__ float d_fea[NN * FIN];
__device__ float d_agg[NN * FIN];
__device__ float d_deg[NN];
__device__ float d_dinv[NN];
__device__ float d_wn[NE];
__device__ float d_hn[NN * 512];
__device__ float d_sims[(size_t)NN * NN];      // 256 MB
__device__ int   d_tidx[NN * KT];
__device__ float d_tval[NN * KT];              // (1-alpha)*relu(sim)
__device__ float d_xw[NN * HIDD];
__device__ float d_h1[NN * HIDD];
__device__ float d_hw[NN * HIDD];
__device__ float d_emb[NN * HIDD];
__device__ float d_sums[NCLS * HIDD];
__device__ float d_cnt[NCLS];
__device__ float d_pn[NCLS * HIDD];

__device__ __forceinline__ float warp_sum(float v) {
#pragma unroll
    for (int o = 16; o > 0; o >>= 1) v += __shfl_xor_sync(0xffffffffu, v, o);
    return v;
}

// ---------------- stage 1: prompt combine + elu --------------------------------
// fea = elu(x * (c0*prompt_spec + c1*shared_tok))
__global__ void k_fea(const float* __restrict__ x, const float* __restrict__ cw,
                      const float* __restrict__ ps, const float* __restrict__ st) {
    int idx = blockIdx.x * 256 + threadIdx.x;
    int f = idx & (FIN - 1);
    float coef = cw[0] * ps[f] + cw[1] * st[f];
    float z = x[idx] * coef;
    d_fea[idx] = z > 0.f ? z : expm1f(z);
}

// ---------------- stage 2: gcn norm -------------------------------------------
__global__ void k_deg_init() {
    int i = blockIdx.x * 256 + threadIdx.x;
    if (i < NN) d_deg[i] = 1.f;   // self loop
}
__global__ void k_deg_acc(const int* __restrict__ dst) {
    int e = blockIdx.x * 256 + threadIdx.x;
    if (e < NE) atomicAdd(&d_deg[dst[e]], 1.f);
}
__global__ void k_dinv() {
    int i = blockIdx.x * 256 + threadIdx.x;
    if (i < NN) d_dinv[i] = 1.f / sqrtf(d_deg[i]);
}
__global__ void k_wn(const int* __restrict__ src, const int* __restrict__ dst) {
    int e = blockIdx.x * 256 + threadIdx.x;
    if (e < NE) d_wn[e] = d_dinv[src[e]] * d_dinv[dst[e]];
}

// ---------------- stage 3: aggregate ------------------------------------------
__global__ void k_agg_init() {   // self-loop term also serves as the zero-init
    int idx = blockIdx.x * 256 + threadIdx.x;
    int i = idx >> 8;
    float di = d_dinv[i];
    d_agg[idx] = di * di * d_fea[idx];
}
__global__ void k_agg_scatter(const int* __restrict__ src, const int* __restrict__ dst) {
    int w = (blockIdx.x * 256 + threadIdx.x) >> 5;
    int lane = threadIdx.x & 31;
    if (w >= NE) return;
    int s = src[w], d = dst[w];
    float wt = d_wn[w];
    const float* fs = d_fea + (size_t)s * FIN;
    float* ad = d_agg + (size_t)d * FIN;
#pragma unroll
    for (int q = 0; q < 8; q++) { int f = lane + 32 * q; atomicAdd(&ad[f], wt * fs[f]); }
}

// ---------------- stage 4: h = concat(fea, agg)*bal, row-normalized ------------
__global__ void k_h(const float* __restrict__ bal) {
    int row = blockIdx.x, t = threadIdx.x;
    float h0 = d_fea[row * FIN + t] * bal[t];
    float h1 = d_agg[row * FIN + t] * bal[FIN + t];
    __shared__ float red[256];
    red[t] = h0 * h0 + h1 * h1;
    __syncthreads();
    for (int s = 128; s > 0; s >>= 1) { if (t < s) red[t] += red[t + s]; __syncthreads(); }
    float rn = 1.f / (sqrtf(red[0]) + EPSF);
    d_hn[(size_t)row * 512 + t] = h0 * rn;
    d_hn[(size_t)row * 512 + FIN + t] = h1 * rn;
}

// ---------------- stage 5: sims = hn @ hn^T (symmetric SGEMM) ------------------
// 128x128 tile, 256 threads, 8x8 per thread. Upper-triangle blocks only; each
// block writes both C and C^T tiles (bitwise-symmetric sims by construction).
__global__ void k_sgemm_sims() {
    int bi = blockIdx.y, bj = blockIdx.x;
    if (bj < bi) return;
    __shared__ float As[16][132];
    __shared__ float Bs[16][132];
    int tid = threadIdx.x;
    int tm = tid >> 4, tn = tid & 15;
    float acc[8][8];
#pragma unroll
    for (int u = 0; u < 8; u++)
#pragma unroll
        for (int v = 0; v < 8; v++) acc[u][v] = 0.f;

    int r = tid >> 1;
    int kc = (tid & 1) * 8;
    const float* Arow = d_hn + (size_t)(bi * 128 + r) * 512 + kc;
    const float* Brow = d_hn + (size_t)(bj * 128 + r) * 512 + kc;

    for (int k0 = 0; k0 < 512; k0 += 16) {
        float4 a0 = *(const float4*)(Arow + k0);
        float4 a1 = *(const float4*)(Arow + k0 + 4);
        float4 b0 = *(const float4*)(Brow + k0);
        float4 b1 = *(const float4*)(Brow + k0 + 4);
        __syncthreads();
        As[kc + 0][r] = a0.x; As[kc + 1][r] = a0.y; As[kc + 2][r] = a0.z; As[kc + 3][r] = a0.w;
        As[kc + 4][r] = a1.x; As[kc + 5][r] = a1.y; As[kc + 6][r] = a1.z; As[kc + 7][r] = a1.w;
        Bs[kc + 0][r] = b0.x; Bs[kc + 1][r] = b0.y; Bs[kc + 2][r] = b0.z; Bs[kc + 3][r] = b0.w;
        Bs[kc + 4][r] = b1.x; Bs[kc + 5][r] = b1.y; Bs[kc + 6][r] = b1.z; Bs[kc + 7][r] = b1.w;
        __syncthreads();
#pragma unroll
        for (int kk = 0; kk < 16; kk++) {
            float a[8], b[8];
#pragma unroll
            for (int u = 0; u < 8; u++) { a[u] = As[kk][tm * 8 + u]; b[u] = Bs[kk][tn * 8 + u]; }
#pragma unroll
            for (int u = 0; u < 8; u++)
#pragma unroll
                for (int v = 0; v < 8; v++) acc[u][v] += a[u] * b[v];
        }
    }
#pragma unroll
    for (int u = 0; u < 8; u++) {
        int gi = bi * 128 + tm * 8 + u;
#pragma unroll
        for (int v = 0; v < 8; v++) {
            int gj = bj * 128 + tn * 8 + v;
            float c = acc[u][v];
            d_sims[(size_t)gi * NN + gj] = c;
            d_sims[(size_t)gj * NN + gi] = c;   // mirror (identical bits)
        }
    }
}

// ---------------- stage 6: per-row top-17 --------------------------------------
__global__ void k_topk(const float* __restrict__ alphap) {
    int row = blockIdx.x;
    int t = threadIdx.x;
    __shared__ float sv[NN];
    __shared__ float rv[256];
    __shared__ int   ri[256];
    const float* srow = d_sims + (size_t)row * NN;
    for (int f = t; f < NN; f += 256) sv[f] = srow[f];
    __syncthreads();
    float onema = 1.f - *alphap;
    for (int it = 0; it < KT; it++) {
        float bm = -FLT_MAX; int bix = 0x7fffffff;
        for (int f = t; f < NN; f += 256) {
            float v = sv[f];
            if (v > bm) { bm = v; bix = f; }
        }
        rv[t] = bm; ri[t] = bix;
        __syncthreads();
        for (int s = 128; s > 0; s >>= 1) {
            if (t < s) {
                float vo = rv[t + s]; int io = ri[t + s];
                if (vo > rv[t] || (vo == rv[t] && io < ri[t])) { rv[t] = vo; ri[t] = io; }
            }
            __syncthreads();
        }
        if (t == 0) {
            d_tidx[row * KT + it] = ri[0];
            d_tval[row * KT + it] = onema * fmaxf(rv[0], 0.f);  // relu + (1-alpha) fold
            sv[ri[0]] = -FLT_MAX;
        }
        __syncthreads();
    }
}

// ---------------- dense [8192,256]@[256,256] GEMM (feature transforms) ---------
template <int L>
__global__ void k_sgemm_nn(const float* __restrict__ W) {
    const float* A = (L == 0) ? d_fea : d_h1;
    float* C = (L == 0) ? d_xw : d_hw;
    int bm = blockIdx.y, bn = blockIdx.x;
    __shared__ float As[16][132];
    __shared__ float Bs[16][132];
    int tid = threadIdx.x;
    int tm = tid >> 4, tn = tid & 15;
    float acc[8][8];
#pragma unroll
    for (int u = 0; u < 8; u++)
#pragma unroll
        for (int v = 0; v < 8; v++) acc[u][v] = 0.f;
    int r = tid >> 1, kc = (tid & 1) * 8;
    int kb = tid >> 4, nb = (tid & 15) * 8;
    for (int k0 = 0; k0 < 256; k0 += 16) {
        float4 a0 = *(const float4*)&A[(size_t)(bm * 128 + r) * 256 + k0 + kc];
        float4 a1 = *(const float4*)&A[(size_t)(bm * 128 + r) * 256 + k0 + kc + 4];
        float4 b0 = *(const float4*)&W[(size_t)(k0 + kb) * 256 + bn * 128 + nb];
        float4 b1 = *(const float4*)&W[(size_t)(k0 + kb) * 256 + bn * 128 + nb + 4];
        __syncthreads();
        As[kc + 0][r] = a0.x; As[kc + 1][r] = a0.y; As[kc + 2][r] = a0.z; As[kc + 3][r] = a0.w;
        As[kc + 4][r] = a1.x; As[kc + 5][r] = a1.y; As[kc + 6][r] = a1.z; As[kc + 7][r] = a1.w;
        *(float4*)&Bs[kb][nb] = b0;
        *(float4*)&Bs[kb][nb + 4] = b1;
        __syncthreads();
#pragma unroll
        for (int kk = 0; kk < 16; kk++) {
            float a[8], b[8];
#pragma unroll
            for (int u = 0; u < 8; u++) { a[u] = As[kk][tm * 8 + u]; b[u] = Bs[kk][tn * 8 + u]; }
#pragma unroll
            for (int u = 0; u < 8; u++)
#pragma unroll
                for (int v = 0; v < 8; v++) acc[u][v] += a[u] * b[v];
        }
    }
#pragma unroll
    for (int u = 0; u < 8; u++) {
        int gi = bm * 128 + tm * 8 + u;
        float* crow = &C[(size_t)gi * 256 + bn * 128 + tn * 8];
        *(float4*)crow       = make_float4(acc[u][0], acc[u][1], acc[u][2], acc[u][3]);
        *(float4*)(crow + 4) = make_float4(acc[u][4], acc[u][5], acc[u][6], acc[u][7]);
    }
}

// ---------------- sparse A_tot @ X (edge-list SpMM via atomics) -----------------
template <int L>
__global__ void k_spmm_init(const float* __restrict__ alphap) {  // self loops + init
    int idx = blockIdx.x * 256 + threadIdx.x;
    int i = idx >> 8;
    float di = d_dinv[i];
    const float* X = (L == 0) ? d_xw : d_hw;
    float* out = (L == 0) ? d_h1 : d_emb;
    out[idx] = (*alphap) * di * di * X[idx];
}
template <int L>
__global__ void k_spmm_edges(const int* __restrict__ src, const int* __restrict__ dst,
                             const float* __restrict__ alphap) {
    int w = (blockIdx.x * 256 + threadIdx.x) >> 5;
    int lane = threadIdx.x & 31;
    if (w >= NE) return;
    const float* X = (L == 0) ? d_xw : d_hw;
    float* out = (L == 0) ? d_h1 : d_emb;
    int s = src[w], d = dst[w];
    float wt = (*alphap) * d_wn[w];
    const float* xs = X + (size_t)s * HIDD;
    float* od = out + (size_t)d * HIDD;
#pragma unroll
    for (int q = 0; q < 8; q++) { int f = lane + 32 * q; atomicAdd(&od[f], wt * xs[f]); }
}
// kNN part of A_tot: entry (i, j=topk(i)[k]) contributes to rows i and j; the
// mirror into row j is skipped when i ∈ topk(j) (that pair emits its own entry).
template <int L>
__global__ void k_spmm_knn() {
    int w = (blockIdx.x * 256 + threadIdx.x) >> 5;
    int lane = threadIdx.x & 31;
    if (w >= NN * KT) return;
    const float* X = (L == 0) ? d_xw : d_hw;
    float* out = (L == 0) ? d_h1 : d_emb;
    int i = w / KT;
    int j = d_tidx[w];
    float v = d_tval[w];
    if (v == 0.f) return;
    const float* xj = X + (size_t)j * HIDD;
    float* oi = out + (size_t)i * HIDD;
#pragma unroll
    for (int q = 0; q < 8; q++) { int f = lane + 32 * q; atomicAdd(&oi[f], v * xj[f]); }
    int cand = (lane < KT) ? d_tidx[j * KT + lane] : -1;
    unsigned found = __ballot_sync(0xffffffffu, cand == i);
    if (!found) {
        const float* xi = X + (size_t)i * HIDD;
        float* oj = out + (size_t)j * HIDD;
#pragma unroll
        for (int q = 0; q < 8; q++) { int f = lane + 32 * q; atomicAdd(&oj[f], v * xi[f]); }
    }
}
__global__ void k_relu() {
    int i = blockIdx.x * 256 + threadIdx.x;
    d_h1[i] = fmaxf(d_h1[i], 0.f);
}

// ---------------- classification ------------------------------------------------
__global__ void k_cls_init() {
    int idx = blockIdx.x * 256 + threadIdx.x;
    if (idx < NCLS * HIDD) d_sums[idx] = 0.f;
    if (idx < NCLS) d_cnt[idx] = 0.f;
}
__global__ void k_cls_scatter(const int* __restrict__ labels, const int* __restrict__ nidx) {
    int w = (blockIdx.x * 256 + threadIdx.x) >> 5;
    int lane = threadIdx.x & 31;
    if (w >= NSEL) return;
    int lbl = labels[w], node = nidx[w];
    const float* er = d_emb + (size_t)node * HIDD;
    float* sr = d_sums + lbl * HIDD;
#pragma unroll
    for (int q = 0; q < 8; q++) { int f = lane + 32 * q; atomicAdd(&sr[f], er[f]); }
    if (lane == 0) atomicAdd(&d_cnt[lbl], 1.f);
}
__global__ void k_proto() {
    int c = blockIdx.x, t = threadIdx.x;
    float cnt = fmaxf(d_cnt[c], 1.f);
    float p = d_sums[c * HIDD + t] / cnt;
    __shared__ float red[256];
    red[t] = p * p;
    __syncthreads();
    for (int s = 128; s > 0; s >>= 1) { if (t < s) red[t] += red[t + s]; __syncthreads(); }
    float rn = 1.f / (sqrtf(red[0]) + EPSF);
    d_pn[c * HIDD + t] = p * rn;
}
__global__ void k_out(const int* __restrict__ nidx, float* __restrict__ out) {
    int w = (blockIdx.x * 256 + threadIdx.x) >> 5;
    int lane = threadIdx.x & 31;
    if (w >= NSEL) return;
    int node = nidx[w];
    const float* er = d_emb + (size_t)node * HIDD;
    float v[8]; float ss = 0.f;
#pragma unroll
    for (int q = 0; q < 8; q++) { v[q] = er[lane + 32 * q]; ss += v[q] * v[q]; }
    ss = warp_sum(ss);
    float rn = 1.f / (sqrtf(ss) + EPSF);
#pragma unroll
    for (int c = 0; c < NCLS; c++) {
        float dp = 0.f;
#pragma unroll
        for (int q = 0; q < 8; q++) dp += v[q] * d_pn[c * HIDD + lane + 32 * q];
        dp = warp_sum(dp);
        if (lane == 0) out[w * NCLS + c] = dp * rn * 5.0f;   // /TEMP, TEMP=0.2
    }
}

// ---------------- launch ---------------------------------------------------------
extern "C" void kernel_launch(void* const* d_in, const int* in_sizes, int n_in,
                              void* d_out, int out_size) {
    const float* x   = (const float*)d_in[0];
    const float* cw  = (const float*)d_in[1];
    const float* alp = (const float*)d_in[2];
    const float* ps  = (const float*)d_in[3];
    const float* st  = (const float*)d_in[4];
    const float* bal = (const float*)d_in[5];
    const float* W1  = (const float*)d_in[6];
    const float* W2  = (const float*)d_in[7];
    const int*   ei  = (const int*)d_in[8];
    const int*   lab = (const int*)d_in[9];
    const int*   nix = (const int*)d_in[10];
    float* out = (float*)d_out;
    const int* esrc = ei;
    const int* edst = ei + NE;

    k_fea<<<NN * FIN / 256, 256>>>(x, cw, ps, st);
    k_deg_init<<<NN / 256, 256>>>();
    k_deg_acc<<<NE / 256, 256>>>(edst);
    k_dinv<<<NN / 256, 256>>>();
    k_wn<<<NE / 256, 256>>>(esrc, edst);
    k_agg_init<<<NN * FIN / 256, 256>>>();
    k_agg_scatter<<<NE / 8, 256>>>(esrc, edst);
    k_h<<<NN, 256>>>(bal);
    k_sgemm_sims<<<dim3(64, 64), 256>>>();
    k_topk<<<NN, 256>>>(alp);

    k_sgemm_nn<0><<<dim3(2, 64), 256>>>(W1);
    k_spmm_init<0><<<NN * HIDD / 256, 256>>>(alp);
    k_spmm_edges<0><<<NE / 8, 256>>>(esrc, edst, alp);
    k_spmm_knn<0><<<NN * KT / 8, 256>>>();
    k_relu<<<NN * HIDD / 256, 256>>>();

    k_sgemm_nn<1><<<dim3(2, 64), 256>>>(W2);
    k_spmm_init<1><<<NN * HIDD / 256, 256>>>(alp);
    k_spmm_edges<1><<<NE / 8, 256>>>(esrc, edst, alp);
    k_spmm_knn<1><<<NN * KT / 8, 256>>>();

    k_cls_init<<<(NCLS * HIDD + 255) / 256, 256>>>();
    k_cls_scatter<<<NSEL / 8, 256>>>(lab, nix);
    k_proto<<<NCLS, 256>>>();
    k_out<<<NSEL / 8, 256>>>(nix, out);
}

// round 2
// speedup vs baseline: 1.0013x; 1.0013x over previous
#include <cuda_runtime.h>
#include <math.h>
#include <float.h>

#define NN   8192
#define FIN  256
#define HIDD 256
#define NE   131072
#define KT   17
#define NCLS 10
#define NSEL 4096
#define EPSF 1e-8f

// ---------------- scratch (static device allocations; no runtime alloc) ---------
__device__ float d_fea[NN * FIN];
__device__ float d_agg[NN * FIN];
__device__ float d_deg[NN];
__device__ float d_dinv[NN];
__device__ float d_wn[NE];
__device__ float d_hn[NN * 512];
__device__ float d_sims[(size_t)NN * NN];      // 256 MB
__device__ int   d_tidx[NN * KT];
__device__ float d_tval[NN * KT];              // (1-alpha)*relu(sim)
__device__ float d_xw[NN * HIDD];
__device__ float d_h1[NN * HIDD];
__device__ float d_hw[NN * HIDD];
__device__ float d_emb[NN * HIDD];
__device__ float d_sums[NCLS * HIDD];
__device__ float d_cnt[NCLS];
__device__ float d_pn[NCLS * HIDD];

__device__ __forceinline__ float warp_sum(float v) {
#pragma unroll
    for (int o = 16; o > 0; o >>= 1) v += __shfl_xor_sync(0xffffffffu, v, o);
    return v;
}

// ---------------- stage 1: prompt combine + elu --------------------------------
// fea = elu(x * (c0*prompt_spec + c1*shared_tok))
__global__ void k_fea(const float* __restrict__ x, const float* __restrict__ cw,
                      const float* __restrict__ ps, const float* __restrict__ st) {
    int idx = blockIdx.x * 256 + threadIdx.x;
    int f = idx & (FIN - 1);
    float coef = cw[0] * ps[f] + cw[1] * st[f];
    float z = x[idx] * coef;
    d_fea[idx] = z > 0.f ? z : expm1f(z);
}

// ---------------- stage 2: gcn norm -------------------------------------------
__global__ void k_deg_init() {
    int i = blockIdx.x * 256 + threadIdx.x;
    if (i < NN) d_deg[i] = 1.f;   // self loop
}
__global__ void k_deg_acc(const int* __restrict__ dst) {
    int e = blockIdx.x * 256 + threadIdx.x;
    if (e < NE) atomicAdd(&d_deg[dst[e]], 1.f);
}
__global__ void k_dinv() {
    int i = blockIdx.x * 256 + threadIdx.x;
    if (i < NN) d_dinv[i] = 1.f / sqrtf(d_deg[i]);
}
__global__ void k_wn(const int* __restrict__ src, const int* __restrict__ dst) {
    int e = blockIdx.x * 256 + threadIdx.x;
    if (e < NE) d_wn[e] = d_dinv[src[e]] * d_dinv[dst[e]];
}

// ---------------- stage 3: aggregate ------------------------------------------
__global__ void k_agg_init() {   // self-loop term also serves as the zero-init
    int idx = blockIdx.x * 256 + threadIdx.x;
    int i = idx >> 8;
    float di = d_dinv[i];
    d_agg[idx] = di * di * d_fea[idx];
}
__global__ void k_agg_scatter(const int* __restrict__ src, const int* __restrict__ dst) {
    int w = (blockIdx.x * 256 + threadIdx.x) >> 5;
    int lane = threadIdx.x & 31;
    if (w >= NE) return;
    int s = src[w], d = dst[w];
    float wt = d_wn[w];
    const float* fs = d_fea + (size_t)s * FIN;
    float* ad = d_agg + (size_t)d * FIN;
#pragma unroll
    for (int q = 0; q < 8; q++) { int f = lane + 32 * q; atomicAdd(&ad[f], wt * fs[f]); }
}

// ---------------- stage 4: h = concat(fea, agg)*bal, row-normalized ------------
__global__ void k_h(const float* __restrict__ bal) {
    int row = blockIdx.x, t = threadIdx.x;
    float h0 = d_fea[row * FIN + t] * bal[t];
    float h1 = d_agg[row * FIN + t] * bal[FIN + t];
    __shared__ float red[256];
    red[t] = h0 * h0 + h1 * h1;
    __syncthreads();
    for (int s = 128; s > 0; s >>= 1) { if (t < s) red[t] += red[t + s]; __syncthreads(); }
    float rn = 1.f / (sqrtf(red[0]) + EPSF);
    d_hn[(size_t)row * 512 + t] = h0 * rn;
    d_hn[(size_t)row * 512 + FIN + t] = h1 * rn;
}

// ---------------- stage 5: sims = hn @ hn^T (symmetric SGEMM) ------------------
// 128x128 tile, 256 threads, 8x8 per thread. Upper-triangle blocks only; each
// block writes both C and C^T tiles (bitwise-symmetric sims by construction).
__global__ void k_sgemm_sims() {
    int bi = blockIdx.y, bj = blockIdx.x;
    if (bj < bi) return;
    __shared__ float As[16][132];
    __shared__ float Bs[16][132];
    int tid = threadIdx.x;
    int tm = tid >> 4, tn = tid & 15;
    float acc[8][8];
#pragma unroll
    for (int u = 0; u < 8; u++)
#pragma unroll
        for (int v = 0; v < 8; v++) acc[u][v] = 0.f;

    int r = tid >> 1;
    int kc = (tid & 1) * 8;
    const float* Arow = d_hn + (size_t)(bi * 128 + r) * 512 + kc;
    const float* Brow = d_hn + (size_t)(bj * 128 + r) * 512 + kc;

    for (int k0 = 0; k0 < 512; k0 += 16) {
        float4 a0 = *(const float4*)(Arow + k0);
        float4 a1 = *(const float4*)(Arow + k0 + 4);
        float4 b0 = *(const float4*)(Brow + k0);
        float4 b1 = *(const float4*)(Brow + k0 + 4);
        __syncthreads();
        As[kc + 0][r] = a0.x; As[kc + 1][r] = a0.y; As[kc + 2][r] = a0.z; As[kc + 3][r] = a0.w;
        As[kc + 4][r] = a1.x; As[kc + 5][r] = a1.y; As[kc + 6][r] = a1.z; As[kc + 7][r] = a1.w;
        Bs[kc + 0][r] = b0.x; Bs[kc + 1][r] = b0.y; Bs[kc + 2][r] = b0.z; Bs[kc + 3][r] = b0.w;
        Bs[kc + 4][r] = b1.x; Bs[kc + 5][r] = b1.y; Bs[kc + 6][r] = b1.z; Bs[kc + 7][r] = b1.w;
        __syncthreads();
#pragma unroll
        for (int kk = 0; kk < 16; kk++) {
            float a[8], b[8];
#pragma unroll
            for (int u = 0; u < 8; u++) { a[u] = As[kk][tm * 8 + u]; b[u] = Bs[kk][tn * 8 + u]; }
#pragma unroll
            for (int u = 0; u < 8; u++)
#pragma unroll
                for (int v = 0; v < 8; v++) acc[u][v] += a[u] * b[v];
        }
    }
#pragma unroll
    for (int u = 0; u < 8; u++) {
        int gi = bi * 128 + tm * 8 + u;
#pragma unroll
        for (int v = 0; v < 8; v++) {
            int gj = bj * 128 + tn * 8 + v;
            float c = acc[u][v];
            d_sims[(size_t)gi * NN + gj] = c;
            d_sims[(size_t)gj * NN + gi] = c;   // mirror (identical bits)
        }
    }
}

// ---------------- stage 6: per-row top-17 --------------------------------------
__global__ void k_topk(const float* __restrict__ alphap) {
    int row = blockIdx.x;
    int t = threadIdx.x;
    __shared__ float sv[NN];
    __shared__ float rv[256];
    __shared__ int   ri[256];
    const float* srow = d_sims + (size_t)row * NN;
    for (int f = t; f < NN; f += 256) sv[f] = srow[f];
    __syncthreads();
    float onema = 1.f - *alphap;
    for (int it = 0; it < KT; it++) {
        float bm = -FLT_MAX; int bix = 0x7fffffff;
        for (int f = t; f < NN; f += 256) {
            float v = sv[f];
            if (v > bm) { bm = v; bix = f; }
        }
        rv[t] = bm; ri[t] = bix;
        __syncthreads();
        for (int s = 128; s > 0; s >>= 1) {
            if (t < s) {
                float vo = rv[t + s]; int io = ri[t + s];
                if (vo > rv[t] || (vo == rv[t] && io < ri[t])) { rv[t] = vo; ri[t] = io; }
            }
            __syncthreads();
        }
        if (t == 0) {
            d_tidx[row * KT + it] = ri[0];
            d_tval[row * KT + it] = onema * fmaxf(rv[0], 0.f);  // relu + (1-alpha) fold
            sv[ri[0]] = -FLT_MAX;
        }
        __syncthreads();
    }
}

// ---------------- dense [8192,256]@[256,256] GEMM (feature transforms) ---------
template <int L>
__global__ void k_sgemm_nn(const float* __restrict__ W) {
    const float* A = (L == 0) ? d_fea : d_h1;
    float* C = (L == 0) ? d_xw : d_hw;
    int bm = blockIdx.y, bn = blockIdx.x;
    __shared__ float As[16][132];
    __shared__ float Bs[16][132];
    int tid = threadIdx.x;
    int tm = tid >> 4, tn = tid & 15;
    float acc[8][8];
#pragma unroll
    for (int u = 0; u < 8; u++)
#pragma unroll
        for (int v = 0; v < 8; v++) acc[u][v] = 0.f;
    int r = tid >> 1, kc = (tid & 1) * 8;
    int kb = tid >> 4, nb = (tid & 15) * 8;
    for (int k0 = 0; k0 < 256; k0 += 16) {
        float4 a0 = *(const float4*)&A[(size_t)(bm * 128 + r) * 256 + k0 + kc];
        float4 a1 = *(const float4*)&A[(size_t)(bm * 128 + r) * 256 + k0 + kc + 4];
        float4 b0 = *(const float4*)&W[(size_t)(k0 + kb) * 256 + bn * 128 + nb];
        float4 b1 = *(const float4*)&W[(size_t)(k0 + kb) * 256 + bn * 128 + nb + 4];
        __syncthreads();
        As[kc + 0][r] = a0.x; As[kc + 1][r] = a0.y; As[kc + 2][r] = a0.z; As[kc + 3][r] = a0.w;
        As[kc + 4][r] = a1.x; As[kc + 5][r] = a1.y; As[kc + 6][r] = a1.z; As[kc + 7][r] = a1.w;
        *(float4*)&Bs[kb][nb] = b0;
        *(float4*)&Bs[kb][nb + 4] = b1;
        __syncthreads();
#pragma unroll
        for (int kk = 0; kk < 16; kk++) {
            float a[8], b[8];
#pragma unroll
            for (int u = 0; u < 8; u++) { a[u] = As[kk][tm * 8 + u]; b[u] = Bs[kk][tn * 8 + u]; }
#pragma unroll
            for (int u = 0; u < 8; u++)
#pragma unroll
                for (int v = 0; v < 8; v++) acc[u][v] += a[u] * b[v];
        }
    }
#pragma unroll
    for (int u = 0; u < 8; u++) {
        int gi = bm * 128 + tm * 8 + u;
        float* crow = &C[(size_t)gi * 256 + bn * 128 + tn * 8];
        *(float4*)crow       = make_float4(acc[u][0], acc[u][1], acc[u][2], acc[u][3]);
        *(float4*)(crow + 4) = make_float4(acc[u][4], acc[u][5], acc[u][6], acc[u][7]);
    }
}

// ---------------- sparse A_tot @ X (edge-list SpMM via atomics) -----------------
template <int L>
__global__ void k_spmm_init(const float* __restrict__ alphap) {  // self loops + init
    int idx = blockIdx.x * 256 + threadIdx.x;
    int i = idx >> 8;
    float di = d_dinv[i];
    const float* X = (L == 0) ? d_xw : d_hw;
    float* out = (L == 0) ? d_h1 : d_emb;
    out[idx] = (*alphap) * di * di * X[idx];
}
template <int L>
__global__ void k_spmm_edges(const int* __restrict__ src, const int* __restrict__ dst,
                             const float* __restrict__ alphap) {
    int w = (blockIdx.x * 256 + threadIdx.x) >> 5;
    int lane = threadIdx.x & 31;
    if (w >= NE) return;
    const float* X = (L == 0) ? d_xw : d_hw;
    float* out = (L == 0) ? d_h1 : d_emb;
    int s = src[w], d = dst[w];
    float wt = (*alphap) * d_wn[w];
    const float* xs = X + (size_t)s * HIDD;
    float* od = out + (size_t)d * HIDD;
#pragma unroll
    for (int q = 0; q < 8; q++) { int f = lane + 32 * q; atomicAdd(&od[f], wt * xs[f]); }
}
// kNN part of A_tot: entry (i, j=topk(i)[k]) contributes to rows i and j; the
// mirror into row j is skipped when i ∈ topk(j) (that pair emits its own entry).
template <int L>
__global__ void k_spmm_knn() {
    int w = (blockIdx.x * 256 + threadIdx.x) >> 5;
    int lane = threadIdx.x & 31;
    if (w >= NN * KT) return;
    const float* X = (L == 0) ? d_xw : d_hw;
    float* out = (L == 0) ? d_h1 : d_emb;
    int i = w / KT;
    int j = d_tidx[w];
    float v = d_tval[w];
    if (v == 0.f) return;
    const float* xj = X + (size_t)j * HIDD;
    float* oi = out + (size_t)i * HIDD;
#pragma unroll
    for (int q = 0; q < 8; q++) { int f = lane + 32 * q; atomicAdd(&oi[f], v * xj[f]); }
    int cand = (lane < KT) ? d_tidx[j * KT + lane] : -1;
    unsigned found = __ballot_sync(0xffffffffu, cand == i);
    if (!found) {
        const float* xi = X + (size_t)i * HIDD;
        float* oj = out + (size_t)j * HIDD;
#pragma unroll
        for (int q = 0; q < 8; q++) { int f = lane + 32 * q; atomicAdd(&oj[f], v * xi[f]); }
    }
}
__global__ void k_relu() {
    int i = blockIdx.x * 256 + threadIdx.x;
    d_h1[i] = fmaxf(d_h1[i], 0.f);
}

// ---------------- classification ------------------------------------------------
__global__ void k_cls_init() {
    int idx = blockIdx.x * 256 + threadIdx.x;
    if (idx < NCLS * HIDD) d_sums[idx] = 0.f;
    if (idx < NCLS) d_cnt[idx] = 0.f;
}
__global__ void k_cls_scatter(const int* __restrict__ labels, const int* __restrict__ nidx) {
    int w = (blockIdx.x * 256 + threadIdx.x) >> 5;
    int lane = threadIdx.x & 31;
    if (w >= NSEL) return;
    int lbl = labels[w], node = nidx[w];
    const float* er = d_emb + (size_t)node * HIDD;
    float* sr = d_sums + lbl * HIDD;
#pragma unroll
    for (int q = 0; q < 8; q++) { int f = lane + 32 * q; atomicAdd(&sr[f], er[f]); }
    if (lane == 0) atomicAdd(&d_cnt[lbl], 1.f);
}
__global__ void k_proto() {
    int c = blockIdx.x, t = threadIdx.x;
    float cnt = fmaxf(d_cnt[c], 1.f);
    float p = d_sums[c * HIDD + t] / cnt;
    __shared__ float red[256];
    red[t] = p * p;
    __syncthreads();
    for (int s = 128; s > 0; s >>= 1) { if (t < s) red[t] += red[t + s]; __syncthreads(); }
    float rn = 1.f / (sqrtf(red[0]) + EPSF);
    d_pn[c * HIDD + t] = p * rn;
}
__global__ void k_out(const int* __restrict__ nidx, float* __restrict__ out) {
    int w = (blockIdx.x * 256 + threadIdx.x) >> 5;
    int lane = threadIdx.x & 31;
    if (w >= NSEL) return;
    int node = nidx[w];
    const float* er = d_emb + (size_t)node * HIDD;
    float v[8]; float ss = 0.f;
#pragma unroll
    for (int q = 0; q < 8; q++) { v[q] = er[lane + 32 * q]; ss += v[q] * v[q]; }
    ss = warp_sum(ss);
    float rn = 1.f / (sqrtf(ss) + EPSF);
#pragma unroll
    for (int c = 0; c < NCLS; c++) {
        float dp = 0.f;
#pragma unroll
        for (int q = 0; q < 8; q++) dp += v[q] * d_pn[c * HIDD + lane + 32 * q];
        dp = warp_sum(dp);
        if (lane == 0) out[w * NCLS + c] = dp * rn * 5.0f;   // /TEMP, TEMP=0.2
    }
}

// ---------------- launch ---------------------------------------------------------
extern "C" void kernel_launch(void* const* d_in, const int* in_sizes, int n_in,
                              void* d_out, int out_size) {
    const float* x   = (const float*)d_in[0];
    const float* cw  = (const float*)d_in[1];
    const float* alp = (const float*)d_in[2];
    const float* ps  = (const float*)d_in[3];
    const float* st  = (const float*)d_in[4];
    const float* bal = (const float*)d_in[5];
    const float* W1  = (const float*)d_in[6];
    const float* W2  = (const float*)d_in[7];
    const int*   ei  = (const int*)d_in[8];
    const int*   lab = (const int*)d_in[9];
    const int*   nix = (const int*)d_in[10];
    float* out = (float*)d_out;
    const int* esrc = ei;
    const int* edst = ei + NE;

    k_fea<<<NN * FIN / 256, 256>>>(x, cw, ps, st);
    k_deg_init<<<NN / 256, 256>>>();
    k_deg_acc<<<NE / 256, 256>>>(edst);
    k_dinv<<<NN / 256, 256>>>();
    k_wn<<<NE / 256, 256>>>(esrc, edst);
    k_agg_init<<<NN * FIN / 256, 256>>>();
    k_agg_scatter<<<NE / 8, 256>>>(esrc, edst);
    k_h<<<NN, 256>>>(bal);
    k_sgemm_sims<<<dim3(64, 64), 256>>>();
    k_topk<<<NN, 256>>>(alp);

    k_sgemm_nn<0><<<dim3(2, 64), 256>>>(W1);
    k_spmm_init<0><<<NN * HIDD / 256, 256>>>(alp);
    k_spmm_edges<0><<<NE / 8, 256>>>(esrc, edst, alp);
    k_spmm_knn<0><<<NN * KT / 8, 256>>>();
    k_relu<<<NN * HIDD / 256, 256>>>();

    k_sgemm_nn<1><<<dim3(2, 64), 256>>>(W2);
    k_spmm_init<1><<<NN * HIDD / 256, 256>>>(alp);
    k_spmm_edges<1><<<NE / 8, 256>>>(esrc, edst, alp);
    k_spmm_knn<1><<<NN * KT / 8, 256>>>();

    k_cls_init<<<(NCLS * HIDD + 255) / 256, 256>>>();
    k_cls_scatter<<<NSEL / 8, 256>>>(lab, nix);
    k_proto<<<NCLS, 256>>>();
    k_out<<<NSEL / 8, 256>>>(nix, out);
}

// round 4
// speedup vs baseline: 1.6672x; 1.6650x over previous
#include <cuda_runtime.h>
#include <cuda_bf16.h>
#include <math.h>
#include <float.h>
#include <stdint.h>

#define NN   8192
#define FIN  256
#define HIDD 256
#define NE   131072
#define KT   17
#define NCAND 24
#define NCLS 10
#define NSEL 4096
#define EPSF 1e-8f

__device__ __align__(16) float d_fea[NN * FIN];
__device__ __align__(16) float d_agg[NN * FIN];
__device__ float d_deg[NN];
__device__ float d_dinv[NN];
__device__ float d_wn[NE];
__device__ __align__(16) float d_hn[NN * 512];
__device__ __align__(16) __nv_bfloat16 d_hb[NN * 512];
__device__ float d_sims[(size_t)NN * NN];
__device__ int   d_tidx[NN * KT];
__device__ float d_tval[NN * KT];
__device__ __align__(16) float d_xw[NN * HIDD];
__device__ __align__(16) float d_h1[NN * HIDD];
__device__ __align__(16) float d_hw[NN * HIDD];
__device__ __align__(16) float d_emb[NN * HIDD];
__device__ __align__(16) float d_sums[NCLS * HIDD];
__device__ float d_cnt[NCLS];
__device__ float d_pn[NCLS * HIDD];

__device__ __forceinline__ float warp_sum(float v) {
#pragma unroll
    for (int o = 16; o > 0; o >>= 1) v += __shfl_xor_sync(0xffffffffu, v, o);
    return v;
}
__device__ __forceinline__ void red4(float4* addr, float a, float b, float c, float d) {
    asm volatile("red.global.add.v4.f32 [%0], {%1,%2,%3,%4};"
                 :: "l"(addr), "f"(a), "f"(b), "f"(c), "f"(d) : "memory");
}

// -------- stage 1: fea = elu(x * (c0*ps + c1*st)) --------
__global__ void k_fea(const float* __restrict__ x, const float* __restrict__ cw,
                      const float* __restrict__ ps, const float* __restrict__ st) {
    int idx = blockIdx.x * 256 + threadIdx.x;
    int f = idx & (FIN - 1);
    float z = x[idx] * (cw[0] * ps[f] + cw[1] * st[f]);
    d_fea[idx] = z > 0.f ? z : expm1f(z);
}
// -------- stage 2: gcn norm --------
__global__ void k_deg_init() { int i = blockIdx.x*256+threadIdx.x; if (i<NN) d_deg[i]=1.f; }
__global__ void k_deg_acc(const int* __restrict__ dst) {
    int e = blockIdx.x*256+threadIdx.x; if (e<NE) atomicAdd(&d_deg[dst[e]], 1.f);
}
__global__ void k_dinv() { int i = blockIdx.x*256+threadIdx.x; if (i<NN) d_dinv[i]=1.f/sqrtf(d_deg[i]); }
__global__ void k_wn(const int* __restrict__ src, const int* __restrict__ dst) {
    int e = blockIdx.x*256+threadIdx.x; if (e<NE) d_wn[e]=d_dinv[src[e]]*d_dinv[dst[e]];
}
// -------- stage 3: aggregate --------
__global__ void k_agg_init() {
    int idx = blockIdx.x*256+threadIdx.x;
    float di = d_dinv[idx >> 8];
    d_agg[idx] = di * di * d_fea[idx];
}
__global__ void k_agg_scatter(const int* __restrict__ src, const int* __restrict__ dst) {
    int w = (blockIdx.x*256+threadIdx.x) >> 5, lane = threadIdx.x & 31;
    if (w >= NE) return;
    float wt = d_wn[w];
    const float4* fs = (const float4*)(d_fea + (size_t)src[w]*FIN);
    float4* ad = (float4*)(d_agg + (size_t)dst[w]*FIN);
#pragma unroll
    for (int q = 0; q < 2; q++) {
        int f = lane + 32*q; float4 v = fs[f];
        red4(&ad[f], wt*v.x, wt*v.y, wt*v.z, wt*v.w);
    }
}
// -------- stage 4: normalized h (fp32 + bf16 copy) --------
__global__ void k_h(const float* __restrict__ bal) {
    int row = blockIdx.x, t = threadIdx.x;
    float h0 = d_fea[row*FIN+t] * bal[t];
    float h1 = d_agg[row*FIN+t] * bal[FIN+t];
    __shared__ float red[256];
    red[t] = h0*h0 + h1*h1;
    __syncthreads();
    for (int s = 128; s > 0; s >>= 1) { if (t < s) red[t] += red[t+s]; __syncthreads(); }
    float rn = 1.f / (sqrtf(red[0]) + EPSF);
    float a = h0*rn, b = h1*rn;
    size_t base = (size_t)row * 512;
    d_hn[base+t] = a;        d_hn[base+FIN+t] = b;
    d_hb[base+t] = __float2bfloat16(a);
    d_hb[base+FIN+t] = __float2bfloat16(b);
}

// ======== stage 5: sims = hb @ hb^T via mma.sync (baseline HMMA) ========
__device__ __forceinline__ uint32_t smem_u32(const void* p) {
    uint32_t a;
    asm("{ .reg .u64 t; cvta.to.shared.u64 t, %1; cvt.u32.u64 %0, t; }" : "=r"(a) : "l"(p));
    return a;
}
__device__ __forceinline__ void ldsm4(uint32_t* r, uint32_t addr) {
    asm volatile("ldmatrix.sync.aligned.m8n8.x4.shared.b16 {%0,%1,%2,%3}, [%4];"
                 : "=r"(r[0]), "=r"(r[1]), "=r"(r[2]), "=r"(r[3]) : "r"(addr));
}
__device__ __forceinline__ void mma16816(float* c, const uint32_t* a, uint32_t b0, uint32_t b1) {
    asm volatile("mma.sync.aligned.m16n8k16.row.col.f32.bf16.bf16.f32 "
                 "{%0,%1,%2,%3}, {%4,%5,%6,%7}, {%8,%9}, {%0,%1,%2,%3};"
                 : "+f"(c[0]), "+f"(c[1]), "+f"(c[2]), "+f"(c[3])
                 : "r"(a[0]), "r"(a[1]), "r"(a[2]), "r"(a[3]), "r"(b0), "r"(b1));
}
// smem per stage: A 128x64 bf16 (16KB, 128B rows, XOR-swizzled) + B same
__device__ __forceinline__ void sims_load(uint32_t sbase, const __nv_bfloat16* Ag,
                                          const __nv_bfloat16* Bg, int c, int tid) {
#pragma unroll
    for (int h = 0; h < 2; h++) {
        const __nv_bfloat16* G = h ? Bg : Ag;
        uint32_t base = sbase + (uint32_t)h * 16384;
#pragma unroll
        for (int q = 0; q < 4; q++) {
            int seg = tid + 256 * q;              // 0..1023 : (row, 16B segment)
            int r = seg >> 3, s8 = seg & 7;
            uint32_t dst = base + r * 128 + ((s8 ^ (r & 7)) << 4);
            const char* src = (const char*)(G + (size_t)r * 512 + c * 64 + s8 * 8);
            asm volatile("cp.async.cg.shared.global [%0], [%1], 16;"
                         :: "r"(dst), "l"(src) : "memory");
        }
    }
    asm volatile("cp.async.commit_group;" ::: "memory");
}
#define SIMS_SMEM 66048   // max(2*32KB pipeline, 128*129*4 epilogue)

__global__ void __launch_bounds__(256) k_mma_sims() {
    int bi = blockIdx.y, bj = blockIdx.x;
    if (bj < bi) return;                          // upper-triangle tiles only
    extern __shared__ char smem[];
    uint32_t sb = smem_u32(smem);
    int tid = threadIdx.x;
    int lane = tid & 31, w = tid >> 5;
    int wm = (w & 1) * 64, wn = (w >> 1) * 32;    // warp tile 64x32

    const __nv_bfloat16* Ag = d_hb + (size_t)bi * 128 * 512;
    const __nv_bfloat16* Bg = d_hb + (size_t)bj * 128 * 512;

    float acc[4][4][4];
#pragma unroll
    for (int mt = 0; mt < 4; mt++)
#pragma unroll
        for (int nt = 0; nt < 4; nt++)
#pragma unroll
            for (int e = 0; e < 4; e++) acc[mt][nt][e] = 0.f;

    sims_load(sb, Ag, Bg, 0, tid);
    int lr = lane & 15, lks = lane >> 4;          // ldmatrix row, k-half
    for (int c = 0; c < 8; c++) {
        if (c < 7) sims_load(sb + ((c + 1) & 1) * 32768, Ag, Bg, c + 1, tid);
        if (c < 7) asm volatile("cp.async.wait_group 1;" ::: "memory");
        else       asm volatile("cp.async.wait_group 0;" ::: "memory");
        __syncthreads();
        uint32_t aB = sb + (c & 1) * 32768, bB = aB + 16384;
#pragma unroll
        for (int ks = 0; ks < 4; ks++) {
            int segk = ks * 2 + lks;
            uint32_t a[4][4], b[2][4];
#pragma unroll
            for (int mt = 0; mt < 4; mt++) {
                int r = wm + mt * 16 + lr;
                ldsm4(a[mt], aB + r * 128 + ((segk ^ (r & 7)) << 4));
            }
#pragma unroll
            for (int bt = 0; bt < 2; bt++) {
                int r = wn + bt * 16 + lr;
                ldsm4(b[bt], bB + r * 128 + ((segk ^ (r & 7)) << 4));
            }
#pragma unroll
            for (int mt = 0; mt < 4; mt++)
#pragma unroll
                for (int nt = 0; nt < 4; nt++)
                    mma16816(acc[mt][nt], a[mt], b[nt >> 1][nt & 1], b[nt >> 1][(nt & 1) + 2]);
        }
        __syncthreads();
    }
    // epilogue: frags -> smem (pitch 129, conflict-free transpose) -> gmem
    float* sf = (float*)smem;
    int g = lane >> 2, tq = lane & 3;
#pragma unroll
    for (int mt = 0; mt < 4; mt++)
#pragma unroll
        for (int nt = 0; nt < 4; nt++) {
            int r0 = wm + mt * 16 + g, c0 = wn + nt * 8 + tq * 2;
            sf[r0 * 129 + c0]         = acc[mt][nt][0];
            sf[r0 * 129 + c0 + 1]     = acc[mt][nt][1];
            sf[(r0 + 8) * 129 + c0]     = acc[mt][nt][2];
            sf[(r0 + 8) * 129 + c0 + 1] = acc[mt][nt][3];
        }
    __syncthreads();
    size_t gi0 = (size_t)bi * 128, gj0 = (size_t)bj * 128;
    for (int it = tid; it < 128 * 128; it += 256) {       // direct: gj >= gi
        int r = it >> 7, col = it & 127;
        if (gj0 + col >= gi0 + r)
            d_sims[(gi0 + r) * NN + gj0 + col] = sf[r * 129 + col];
    }
    for (int it = tid; it < 128 * 128; it += 256) {       // mirror: gj > gi
        int j = it >> 7, i2 = it & 127;
        if (gj0 + j > gi0 + i2)
            d_sims[(gj0 + j) * NN + gi0 + i2] = sf[i2 * 129 + j];
    }
}

// -------- stage 6: top-24 approx candidates + exact fp32 rescore -> top-17 -----
__global__ void k_topk(const float* __restrict__ alphap) {
    int row = blockIdx.x, t = threadIdx.x;
    const float* srow = d_sims + (size_t)row * NN;
    float v[32];
#pragma unroll
    for (int q = 0; q < 32; q++) v[q] = srow[q * 256 + t];
    unsigned rem = 0;
    float m = -FLT_MAX; int a = 0;
#pragma unroll
    for (int q = 0; q < 32; q++) if (v[q] > m) { m = v[q]; a = q; }
    __shared__ float wv[8];
    __shared__ int   wi[8];
    __shared__ int   cand[NCAND];
    __shared__ float cex[NCAND];
    for (int it = 0; it < NCAND; it++) {
        float mv = m; int mi = a * 256 + t;
#pragma unroll
        for (int o = 16; o > 0; o >>= 1) {
            float ov = __shfl_xor_sync(0xffffffffu, mv, o);
            int   oi = __shfl_xor_sync(0xffffffffu, mi, o);
            if (ov > mv || (ov == mv && oi < mi)) { mv = ov; mi = oi; }
        }
        if ((t & 31) == 0) { wv[t >> 5] = mv; wi[t >> 5] = mi; }
        __syncthreads();
        if (t == 0) {
            float bv = wv[0]; int bx = wi[0];
#pragma unroll
            for (int k = 1; k < 8; k++)
                if (wv[k] > bv || (wv[k] == bv && wi[k] < bx)) { bv = wv[k]; bx = wi[k]; }
            cand[it] = bx;
        }
        __syncthreads();
        int bx = cand[it];
        if ((bx & 255) == t) {
            rem |= 1u << (bx >> 8);
            m = -FLT_MAX; a = 0;
#pragma unroll
            for (int q = 0; q < 32; q++) {
                float vq = ((rem >> q) & 1u) ? -FLT_MAX : v[q];
                if (vq > m) { m = vq; a = q; }
            }
        }
    }
    // exact fp32 rescore: warp w handles candidates 3w..3w+2
    int w = t >> 5, lane = t & 31;
    const float* hr = d_hn + (size_t)row * 512;
#pragma unroll
    for (int c = w * 3; c < w * 3 + 3; c++) {
        const float* hj = d_hn + (size_t)cand[c] * 512;
        float s = 0.f;
        for (int e = lane; e < 512; e += 32) s += hr[e] * hj[e];
        s = warp_sum(s);
        if (lane == 0) cex[c] = s;
    }
    __syncthreads();
    if (t == 0) {
        float onema = 1.f - *alphap;
        unsigned used = 0;
        for (int it = 0; it < KT; it++) {
            float bv = -FLT_MAX; int bc = -1;
            for (int c = 0; c < NCAND; c++) {
                if ((used >> c) & 1u) continue;
                if (bc < 0 || cex[c] > bv || (cex[c] == bv && cand[c] < cand[bc]))
                    { bv = cex[c]; bc = c; }
            }
            used |= 1u << bc;
            d_tidx[row * KT + it] = cand[bc];
            d_tval[row * KT + it] = onema * fmaxf(bv, 0.f);
        }
    }
}

// -------- dense [8192,256]@[256,256] fp32 GEMM --------
template <int L>
__global__ void k_sgemm_nn(const float* __restrict__ W) {
    const float* A = (L == 0) ? d_fea : d_h1;
    float* C = (L == 0) ? d_xw : d_hw;
    int bm = blockIdx.y, bn = blockIdx.x;
    __shared__ float As[16][132];
    __shared__ float Bs[16][132];
    int tid = threadIdx.x, tm = tid >> 4, tn = tid & 15;
    float acc[8][8];
#pragma unroll
    for (int u = 0; u < 8; u++)
#pragma unroll
        for (int v = 0; v < 8; v++) acc[u][v] = 0.f;
    int r = tid >> 1, kc = (tid & 1) * 8;
    int kb = tid >> 4, nb = (tid & 15) * 8;
    for (int k0 = 0; k0 < 256; k0 += 16) {
        float4 a0 = *(const float4*)&A[(size_t)(bm*128+r)*256 + k0 + kc];
        float4 a1 = *(const float4*)&A[(size_t)(bm*128+r)*256 + k0 + kc + 4];
        float4 b0 = *(const float4*)&W[(size_t)(k0+kb)*256 + bn*128 + nb];
        float4 b1 = *(const float4*)&W[(size_t)(k0+kb)*256 + bn*128 + nb + 4];
        __syncthreads();
        As[kc+0][r]=a0.x; As[kc+1][r]=a0.y; As[kc+2][r]=a0.z; As[kc+3][r]=a0.w;
        As[kc+4][r]=a1.x; As[kc+5][r]=a1.y; As[kc+6][r]=a1.z; As[kc+7][r]=a1.w;
        *(float4*)&Bs[kb][nb] = b0;
        *(float4*)&Bs[kb][nb+4] = b1;
        __syncthreads();
#pragma unroll
        for (int kk = 0; kk < 16; kk++) {
            float av[8], bv[8];
#pragma unroll
            for (int u = 0; u < 8; u++) { av[u]=As[kk][tm*8+u]; bv[u]=Bs[kk][tn*8+u]; }
#pragma unroll
            for (int u = 0; u < 8; u++)
#pragma unroll
                for (int vv = 0; vv < 8; vv++) acc[u][vv] += av[u]*bv[vv];
        }
    }
#pragma unroll
    for (int u = 0; u < 8; u++) {
        float* crow = &C[(size_t)(bm*128+tm*8+u)*256 + bn*128 + tn*8];
        *(float4*)crow     = make_float4(acc[u][0],acc[u][1],acc[u][2],acc[u][3]);
        *(float4*)(crow+4) = make_float4(acc[u][4],acc[u][5],acc[u][6],acc[u][7]);
    }
}

// -------- sparse A_tot @ X --------
template <int L>
__global__ void k_spmm_init(const float* __restrict__ alphap) {
    int idx = blockIdx.x*256+threadIdx.x;
    float di = d_dinv[idx >> 8];
    const float* X = (L == 0) ? d_xw : d_hw;
    float* out = (L == 0) ? d_h1 : d_emb;
    out[idx] = (*alphap) * di * di * X[idx];
}
template <int L>
__global__ void k_spmm_edges(const int* __restrict__ src, const int* __restrict__ dst,
                             const float* __restrict__ alphap) {
    int w = (blockIdx.x*256+threadIdx.x) >> 5, lane = threadIdx.x & 31;
    if (w >= NE) return;
    const float* X = (L == 0) ? d_xw : d_hw;
    float* out = (L == 0) ? d_h1 : d_emb;
    float wt = (*alphap) * d_wn[w];
    const float4* xs = (const float4*)(X + (size_t)src[w]*HIDD);
    float4* od = (float4*)(out + (size_t)dst[w]*HIDD);
#pragma unroll
    for (int q = 0; q < 2; q++) {
        int f = lane + 32*q; float4 v = xs[f];
        red4(&od[f], wt*v.x, wt*v.y, wt*v.z, wt*v.w);
    }
}
template <int L>
__global__ void k_spmm_knn() {
    int w = (blockIdx.x*256+threadIdx.x) >> 5, lane = threadIdx.x & 31;
    if (w >= NN * KT) return;
    const float* X = (L == 0) ? d_xw : d_hw;
    float* out = (L == 0) ? d_h1 : d_emb;
    int i = w / KT, j = d_tidx[w];
    float v = d_tval[w];
    if (v == 0.f) return;
    const float4* xj = (const float4*)(X + (size_t)j*HIDD);
    float4* oi = (float4*)(out + (size_t)i*HIDD);
#pragma unroll
    for (int q = 0; q < 2; q++) {
        int f = lane + 32*q; float4 tv = xj[f];
        red4(&oi[f], v*tv.x, v*tv.y, v*tv.z, v*tv.w);
    }
    int cand = (lane < KT) ? d_tidx[j*KT + lane] : -1;
    if (!__ballot_sync(0xffffffffu, cand == i)) {
        const float4* xi = (const float4*)(X + (size_t)i*HIDD);
        float4* oj = (float4*)(out + (size_t)j*HIDD);
#pragma unroll
        for (int q = 0; q < 2; q++) {
            int f = lane + 32*q; float4 tv = xi[f];
            red4(&oj[f], v*tv.x, v*tv.y, v*tv.z, v*tv.w);
        }
    }
}
__global__ void k_relu() {
    int i = blockIdx.x*256+threadIdx.x;
    d_h1[i] = fmaxf(d_h1[i], 0.f);
}
// -------- classification --------
__global__ void k_cls_init() {
    int idx = blockIdx.x*256+threadIdx.x;
    if (idx < NCLS*HIDD) d_sums[idx] = 0.f;
    if (idx < NCLS) d_cnt[idx] = 0.f;
}
__global__ void k_cls_scatter(const int* __restrict__ labels, const int* __restrict__ nidx) {
    int w = (blockIdx.x*256+threadIdx.x) >> 5, lane = threadIdx.x & 31;
    if (w >= NSEL) return;
    int lbl = labels[w];
    const float4* er = (const float4*)(d_emb + (size_t)nidx[w]*HIDD);
    float4* sr = (float4*)(d_sums + lbl*HIDD);
#pragma unroll
    for (int q = 0; q < 2; q++) {
        int f = lane + 32*q; float4 v = er[f];
        red4(&sr[f], v.x, v.y, v.z, v.w);
    }
    if (lane == 0) atomicAdd(&d_cnt[lbl], 1.f);
}
__global__ void k_proto() {
    int c = blockIdx.x, t = threadIdx.x;
    float p = d_sums[c*HIDD+t] / fmaxf(d_cnt[c], 1.f);
    __shared__ float red[256];
    red[t] = p*p;
    __syncthreads();
    for (int s = 128; s > 0; s >>= 1) { if (t < s) red[t] += red[t+s]; __syncthreads(); }
    d_pn[c*HIDD+t] = p / (sqrtf(red[0]) + EPSF);
}
__global__ void k_out(const int* __restrict__ nidx, float* __restrict__ out) {
    int w = (blockIdx.x*256+threadIdx.x) >> 5, lane = threadIdx.x & 31;
    if (w >= NSEL) return;
    const float* er = d_emb + (size_t)nidx[w]*HIDD;
    float v[8]; float ss = 0.f;
#pragma unroll
    for (int q = 0; q < 8; q++) { v[q] = er[lane+32*q]; ss += v[q]*v[q]; }
    ss = warp_sum(ss);
    float rn = 1.f / (sqrtf(ss) + EPSF);
#pragma unroll
    for (int c = 0; c < NCLS; c++) {
        float dp = 0.f;
#pragma unroll
        for (int q = 0; q < 8; q++) dp += v[q] * d_pn[c*HIDD + lane + 32*q];
        dp = warp_sum(dp);
        if (lane == 0) out[w*NCLS + c] = dp * rn * 5.0f;
    }
}

extern "C" void kernel_launch(void* const* d_in, const int* in_sizes, int n_in,
                              void* d_out, int out_size) {
    const float* x   = (const float*)d_in[0];
    const float* cw  = (const float*)d_in[1];
    const float* alp = (const float*)d_in[2];
    const float* ps  = (const float*)d_in[3];
    const float* st  = (const float*)d_in[4];
    const float* bal = (const float*)d_in[5];
    const float* W1  = (const float*)d_in[6];
    const float* W2  = (const float*)d_in[7];
    const int*   ei  = (const int*)d_in[8];
    const int*   lab = (const int*)d_in[9];
    const int*   nix = (const int*)d_in[10];
    float* out = (float*)d_out;
    const int* esrc = ei;
    const int* edst = ei + NE;

    cudaFuncSetAttribute(k_mma_sims, cudaFuncAttributeMaxDynamicSharedMemorySize, SIMS_SMEM);

    k_fea<<<NN*FIN/256, 256>>>(x, cw, ps, st);
    k_deg_init<<<NN/256, 256>>>();
    k_deg_acc<<<NE/256, 256>>>(edst);
    k_dinv<<<NN/256, 256>>>();
    k_wn<<<NE/256, 256>>>(esrc, edst);
    k_agg_init<<<NN*FIN/256, 256>>>();
    k_agg_scatter<<<NE/8, 256>>>(esrc, edst);
    k_h<<<NN, 256>>>(bal);
    k_mma_sims<<<dim3(64, 64), 256, SIMS_SMEM>>>();
    k_topk<<<NN, 256>>>(alp);

    k_sgemm_nn<0><<<dim3(2, 64), 256>>>(W1);
    k_spmm_init<0><<<NN*HIDD/256, 256>>>(alp);
    k_spmm_edges<0><<<NE/8, 256>>>(esrc, edst, alp);
    k_spmm_knn<0><<<NN*KT/8 + 1, 256>>>();
    k_relu<<<NN*HIDD/256, 256>>>();

    k_sgemm_nn<1><<<dim3(2, 64), 256>>>(W2);
    k_spmm_init<1><<<NN*HIDD/256, 256>>>(alp);
    k_spmm_edges<1><<<NE/8, 256>>>(esrc, edst, alp);
    k_spmm_knn<1><<<NN*KT/8 + 1, 256>>>();

    k_cls_init<<<(NCLS*HIDD+255)/256, 256>>>();
    k_cls_scatter<<<NSEL/8, 256>>>(lab, nix);
    k_proto<<<NCLS, 256>>>();
    k_out<<<NSEL/8, 256>>>(nix, out);
}

// round 5
// speedup vs baseline: 1.7852x; 1.0708x over previous
#include <cuda_runtime.h>
#include <cuda_bf16.h>
#include <math.h>
#include <float.h>
#include <stdint.h>

#define NN   8192
#define FIN  256
#define HIDD 256
#define NE   131072
#define KT   17
#define NCAND 24
#define NCLS 10
#define NSEL 4096
#define EPSF 1e-8f

__device__ __align__(16) float d_fea[NN * FIN];
__device__ float d_dinv[NN];
__device__ int   d_cnt_e[NN];
__device__ int   d_rptr[NN + 1];
__device__ int   d_cur[NN];
__device__ int   d_csrc[NE];
__device__ float d_cw[NE];
__device__ __align__(16) float d_hn[NN * 512];
__device__ __align__(16) __nv_bfloat16 d_hb[NN * 512];
__device__ float d_sims[(size_t)NN * NN];
__device__ int   d_tidx[NN * KT];
__device__ float d_tval[NN * KT];
__device__ int   d_kcnt[NN];
__device__ int   d_kptr[NN + 1];
__device__ int   d_kcur[NN];
__device__ unsigned char d_kmut[NN * KT];
__device__ int   d_kidx[NN * KT * 2];
__device__ float d_kval[NN * KT * 2];
__device__ __align__(16) float d_xw[NN * HIDD];
__device__ __align__(16) float d_h1[NN * HIDD];
__device__ __align__(16) float d_hw[NN * HIDD];
__device__ __align__(16) float d_emb[NN * HIDD];
__device__ __align__(16) float d_sums[NCLS * HIDD];
__device__ float d_cnt[NCLS];
__device__ float d_pn[NCLS * HIDD];

__device__ __forceinline__ float warp_sum(float v) {
#pragma unroll
    for (int o = 16; o > 0; o >>= 1) v += __shfl_xor_sync(0xffffffffu, v, o);
    return v;
}
__device__ __forceinline__ void red4(float4* addr, float a, float b, float c, float d) {
    asm volatile("red.global.add.v4.f32 [%0], {%1,%2,%3,%4};"
                 :: "l"(addr), "f"(a), "f"(b), "f"(c), "f"(d) : "memory");
}
__device__ __forceinline__ void fma4(float4& a, float w, const float4 v) {
    a.x += w * v.x; a.y += w * v.y; a.z += w * v.z; a.w += w * v.w;
}
__device__ __forceinline__ uint2 pack_bf16x4(float4 v) {
    __nv_bfloat162 lo = __floats2bfloat162_rn(v.x, v.y);
    __nv_bfloat162 hi = __floats2bfloat162_rn(v.z, v.w);
    uint2 r;
    r.x = *reinterpret_cast<uint32_t*>(&lo);
    r.y = *reinterpret_cast<uint32_t*>(&hi);
    return r;
}

// -------- stage 1: fea + zero-init of all per-call accumulators --------
__global__ void k_fea(const float* __restrict__ x, const float* __restrict__ cw,
                      const float* __restrict__ ps, const float* __restrict__ st) {
    int idx = blockIdx.x * 256 + threadIdx.x;
    int f = idx & (FIN - 1);
    float z = x[idx] * (cw[0] * ps[f] + cw[1] * st[f]);
    d_fea[idx] = z > 0.f ? z : expm1f(z);
    if (idx < NN) { d_cnt_e[idx] = 0; d_kcnt[idx] = 0; }
    if (idx < NCLS * HIDD) d_sums[idx] = 0.f;
    if (idx < NCLS) d_cnt[idx] = 0.f;
}
// -------- CSR build: count -> scan -> fill --------
__global__ void k_cnt(const int* __restrict__ dst) {
    int e = blockIdx.x * 256 + threadIdx.x;
    if (e < NE) atomicAdd(&d_cnt_e[dst[e]], 1);
}
__global__ void k_scan() {                 // 1 block, 256 threads, 32 rows each
    __shared__ int bs[256];
    int t = threadIdx.x;
    int loc[32]; int s = 0;
#pragma unroll
    for (int q = 0; q < 32; q++) { loc[q] = d_cnt_e[t * 32 + q]; s += loc[q]; }
    bs[t] = s; __syncthreads();
    for (int off = 1; off < 256; off <<= 1) {
        int v = (t >= off) ? bs[t - off] : 0;
        __syncthreads();
        bs[t] += v;
        __syncthreads();
    }
    int run = bs[t] - s;
#pragma unroll
    for (int q = 0; q < 32; q++) {
        int i = t * 32 + q;
        d_rptr[i] = run; d_cur[i] = run;
        d_dinv[i] = rsqrtf((float)(loc[q] + 1));
        run += loc[q];
    }
    if (t == 255) d_rptr[NN] = run;
}
__global__ void k_fill(const int* __restrict__ src, const int* __restrict__ dst) {
    int e = blockIdx.x * 256 + threadIdx.x;
    if (e >= NE) return;
    int s = src[e], d = dst[e];
    int pos = atomicAdd(&d_cur[d], 1);
    d_csrc[pos] = s;
    d_cw[pos] = d_dinv[s] * d_dinv[d];     // gcn-norm weight (fused k_wn)
}
// -------- fused aggregate-gather + h-normalize + bf16 --------
__global__ void k_agg_h(const float* __restrict__ bal) {
    int gw = (blockIdx.x * 256 + threadIdx.x) >> 5, lane = threadIdx.x & 31;
    if (gw >= NN) return;
    float di = d_dinv[gw];
    const float4* fr = (const float4*)(d_fea + (size_t)gw * 256);
    float4 f0 = fr[lane], f1 = fr[lane + 32];
    float sc = di * di;
    float4 a0 = make_float4(sc*f0.x, sc*f0.y, sc*f0.z, sc*f0.w);
    float4 a1 = make_float4(sc*f1.x, sc*f1.y, sc*f1.z, sc*f1.w);
    int b = d_rptr[gw], e = d_rptr[gw + 1];
    for (int p = b; p < e; p++) {
        float wv = d_cw[p];
        const float4* fs = (const float4*)(d_fea + (size_t)d_csrc[p] * 256);
        fma4(a0, wv, fs[lane]); fma4(a1, wv, fs[lane + 32]);
    }
    const float4* bb = (const float4*)bal;
    float4 bA = bb[lane], bB = bb[lane + 32], bC = bb[64 + lane], bD = bb[96 + lane];
    float4 hA = make_float4(f0.x*bA.x, f0.y*bA.y, f0.z*bA.z, f0.w*bA.w);
    float4 hB = make_float4(f1.x*bB.x, f1.y*bB.y, f1.z*bB.z, f1.w*bB.w);
    float4 hC = make_float4(a0.x*bC.x, a0.y*bC.y, a0.z*bC.z, a0.w*bC.w);
    float4 hD = make_float4(a1.x*bD.x, a1.y*bD.y, a1.z*bD.z, a1.w*bD.w);
    float ss = hA.x*hA.x+hA.y*hA.y+hA.z*hA.z+hA.w*hA.w
             + hB.x*hB.x+hB.y*hB.y+hB.z*hB.z+hB.w*hB.w
             + hC.x*hC.x+hC.y*hC.y+hC.z*hC.z+hC.w*hC.w
             + hD.x*hD.x+hD.y*hD.y+hD.z*hD.z+hD.w*hD.w;
    ss = warp_sum(ss);
    float rn = 1.f / (sqrtf(ss) + EPSF);
    hA.x*=rn; hA.y*=rn; hA.z*=rn; hA.w*=rn;
    hB.x*=rn; hB.y*=rn; hB.z*=rn; hB.w*=rn;
    hC.x*=rn; hC.y*=rn; hC.z*=rn; hC.w*=rn;
    hD.x*=rn; hD.y*=rn; hD.z*=rn; hD.w*=rn;
    float4* hr = (float4*)(d_hn + (size_t)gw * 512);
    hr[lane] = hA; hr[lane + 32] = hB; hr[64 + lane] = hC; hr[96 + lane] = hD;
    uint2* hb = (uint2*)(d_hb + (size_t)gw * 512);
    hb[lane] = pack_bf16x4(hA); hb[lane + 32] = pack_bf16x4(hB);
    hb[64 + lane] = pack_bf16x4(hC); hb[96 + lane] = pack_bf16x4(hD);
}

// ======== sims = hb @ hb^T via mma.sync ========
__device__ __forceinline__ uint32_t smem_u32(const void* p) {
    uint32_t a;
    asm("{ .reg .u64 t; cvta.to.shared.u64 t, %1; cvt.u32.u64 %0, t; }" : "=r"(a) : "l"(p));
    return a;
}
__device__ __forceinline__ void ldsm4(uint32_t* r, uint32_t addr) {
    asm volatile("ldmatrix.sync.aligned.m8n8.x4.shared.b16 {%0,%1,%2,%3}, [%4];"
                 : "=r"(r[0]), "=r"(r[1]), "=r"(r[2]), "=r"(r[3]) : "r"(addr));
}
__device__ __forceinline__ void mma16816(float* c, const uint32_t* a, uint32_t b0, uint32_t b1) {
    asm volatile("mma.sync.aligned.m16n8k16.row.col.f32.bf16.bf16.f32 "
                 "{%0,%1,%2,%3}, {%4,%5,%6,%7}, {%8,%9}, {%0,%1,%2,%3};"
                 : "+f"(c[0]), "+f"(c[1]), "+f"(c[2]), "+f"(c[3])
                 : "r"(a[0]), "r"(a[1]), "r"(a[2]), "r"(a[3]), "r"(b0), "r"(b1));
}
__device__ __forceinline__ void sims_load(uint32_t sbase, const __nv_bfloat16* Ag,
                                          const __nv_bfloat16* Bg, int c, int tid) {
#pragma unroll
    for (int h = 0; h < 2; h++) {
        const __nv_bfloat16* G = h ? Bg : Ag;
        uint32_t base = sbase + (uint32_t)h * 16384;
#pragma unroll
        for (int q = 0; q < 4; q++) {
            int seg = tid + 256 * q;
            int r = seg >> 3, s8 = seg & 7;
            uint32_t dst = base + r * 128 + ((s8 ^ (r & 7)) << 4);
            const char* src = (const char*)(G + (size_t)r * 512 + c * 64 + s8 * 8);
            asm volatile("cp.async.cg.shared.global [%0], [%1], 16;"
                         :: "r"(dst), "l"(src) : "memory");
        }
    }
    asm volatile("cp.async.commit_group;" ::: "memory");
}
#define SIMS_SMEM 66048

__global__ void __launch_bounds__(256, 2) k_mma_sims() {
    int bi = blockIdx.y, bj = blockIdx.x;
    if (bj < bi) return;
    extern __shared__ char smem[];
    uint32_t sb = smem_u32(smem);
    int tid = threadIdx.x;
    int lane = tid & 31, w = tid >> 5;
    int wm = (w & 1) * 64, wn = (w >> 1) * 32;

    const __nv_bfloat16* Ag = d_hb + (size_t)bi * 128 * 512;
    const __nv_bfloat16* Bg = d_hb + (size_t)bj * 128 * 512;

    float acc[4][4][4];
#pragma unroll
    for (int mt = 0; mt < 4; mt++)
#pragma unroll
        for (int nt = 0; nt < 4; nt++)
#pragma unroll
            for (int e = 0; e < 4; e++) acc[mt][nt][e] = 0.f;

    sims_load(sb, Ag, Bg, 0, tid);
    int lr = lane & 15, lks = lane >> 4;
    for (int c = 0; c < 8; c++) {
        if (c < 7) sims_load(sb + ((c + 1) & 1) * 32768, Ag, Bg, c + 1, tid);
        if (c < 7) asm volatile("cp.async.wait_group 1;" ::: "memory");
        else       asm volatile("cp.async.wait_group 0;" ::: "memory");
        __syncthreads();
        uint32_t aB = sb + (c & 1) * 32768, bB = aB + 16384;
#pragma unroll
        for (int ks = 0; ks < 4; ks++) {
            int segk = ks * 2 + lks;
            uint32_t a[4][4], b[2][4];
#pragma unroll
            for (int mt = 0; mt < 4; mt++) {
                int r = wm + mt * 16 + lr;
                ldsm4(a[mt], aB + r * 128 + ((segk ^ (r & 7)) << 4));
            }
#pragma unroll
            for (int bt = 0; bt < 2; bt++) {
                int r = wn + bt * 16 + lr;
                ldsm4(b[bt], bB + r * 128 + ((segk ^ (r & 7)) << 4));
            }
#pragma unroll
            for (int mt = 0; mt < 4; mt++)
#pragma unroll
                for (int nt = 0; nt < 4; nt++)
                    mma16816(acc[mt][nt], a[mt], b[nt >> 1][nt & 1], b[nt >> 1][(nt & 1) + 2]);
        }
        __syncthreads();
    }
    float* sf = (float*)smem;
    int g = lane >> 2, tq = lane & 3;
#pragma unroll
    for (int mt = 0; mt < 4; mt++)
#pragma unroll
        for (int nt = 0; nt < 4; nt++) {
            int r0 = wm + mt * 16 + g, c0 = wn + nt * 8 + tq * 2;
            sf[r0 * 129 + c0]           = acc[mt][nt][0];
            sf[r0 * 129 + c0 + 1]       = acc[mt][nt][1];
            sf[(r0 + 8) * 129 + c0]     = acc[mt][nt][2];
            sf[(r0 + 8) * 129 + c0 + 1] = acc[mt][nt][3];
        }
    __syncthreads();
    size_t gi0 = (size_t)bi * 128, gj0 = (size_t)bj * 128;
    for (int it = tid; it < 128 * 128; it += 256) {
        int r = it >> 7, col = it & 127;
        if (gj0 + col >= gi0 + r)
            d_sims[(gi0 + r) * NN + gj0 + col] = sf[r * 129 + col];
    }
    for (int it = tid; it < 128 * 128; it += 256) {
        int j = it >> 7, i2 = it & 127;
        if (gj0 + j > gi0 + i2)
            d_sims[(gj0 + j) * NN + gi0 + i2] = sf[i2 * 129 + j];
    }
}

// -------- top-24 approx + exact fp32 rescore -> top-17 --------
__global__ void k_topk(const float* __restrict__ alphap) {
    int row = blockIdx.x, t = threadIdx.x;
    const float* srow = d_sims + (size_t)row * NN;
    float v[32];
#pragma unroll
    for (int q = 0; q < 32; q++) v[q] = srow[q * 256 + t];
    unsigned rem = 0;
    float m = -FLT_MAX; int a = 0;
#pragma unroll
    for (int q = 0; q < 32; q++) if (v[q] > m) { m = v[q]; a = q; }
    __shared__ float wv[8];
    __shared__ int   wi[8];
    __shared__ int   cand[NCAND];
    __shared__ float cex[NCAND];
    for (int it = 0; it < NCAND; it++) {
        float mv = m; int mi = a * 256 + t;
#pragma unroll
        for (int o = 16; o > 0; o >>= 1) {
            float ov = __shfl_xor_sync(0xffffffffu, mv, o);
            int   oi = __shfl_xor_sync(0xffffffffu, mi, o);
            if (ov > mv || (ov == mv && oi < mi)) { mv = ov; mi = oi; }
        }
        if ((t & 31) == 0) { wv[t >> 5] = mv; wi[t >> 5] = mi; }
        __syncthreads();
        if (t == 0) {
            float bv = wv[0]; int bx = wi[0];
#pragma unroll
            for (int k = 1; k < 8; k++)
                if (wv[k] > bv || (wv[k] == bv && wi[k] < bx)) { bv = wv[k]; bx = wi[k]; }
            cand[it] = bx;
        }
        __syncthreads();
        int bx = cand[it];
        if ((bx & 255) == t) {
            rem |= 1u << (bx >> 8);
            m = -FLT_MAX; a = 0;
#pragma unroll
            for (int q = 0; q < 32; q++) {
                float vq = ((rem >> q) & 1u) ? -FLT_MAX : v[q];
                if (vq > m) { m = vq; a = q; }
            }
        }
    }
    int w = t >> 5, lane = t & 31;
    const float* hr = d_hn + (size_t)row * 512;
#pragma unroll
    for (int c = w * 3; c < w * 3 + 3; c++) {
        const float* hj = d_hn + (size_t)cand[c] * 512;
        float s = 0.f;
        for (int e = lane; e < 512; e += 32) s += hr[e] * hj[e];
        s = warp_sum(s);
        if (lane == 0) cex[c] = s;
    }
    __syncthreads();
    if (t == 0) {
        float onema = 1.f - *alphap;
        unsigned used = 0;
        for (int it = 0; it < KT; it++) {
            float bv = -FLT_MAX; int bc = -1;
            for (int c = 0; c < NCAND; c++) {
                if ((used >> c) & 1u) continue;
                if (bc < 0 || cex[c] > bv || (cex[c] == bv && cand[c] < cand[bc]))
                    { bv = cex[c]; bc = c; }
            }
            used |= 1u << bc;
            d_tidx[row * KT + it] = cand[bc];
            d_tval[row * KT + it] = onema * fmaxf(bv, 0.f);
        }
    }
}

// -------- kNN symmetric CSR build --------
__global__ void k_kcount() {
    int w = (blockIdx.x * 256 + threadIdx.x) >> 5, lane = threadIdx.x & 31;
    if (w >= NN * KT) return;
    int i = w / KT, j = d_tidx[w];
    int cand = (lane < KT) ? d_tidx[j * KT + lane] : -1;
    unsigned f = __ballot_sync(0xffffffffu, cand == i);
    if (lane == 0) {
        atomicAdd(&d_kcnt[i], 1);
        d_kmut[w] = (f != 0);
        if (!f) atomicAdd(&d_kcnt[j], 1);
    }
}
__global__ void k_kscan() {
    __shared__ int bs[256];
    int t = threadIdx.x;
    int loc[32]; int s = 0;
#pragma unroll
    for (int q = 0; q < 32; q++) { loc[q] = d_kcnt[t * 32 + q]; s += loc[q]; }
    bs[t] = s; __syncthreads();
    for (int off = 1; off < 256; off <<= 1) {
        int v = (t >= off) ? bs[t - off] : 0;
        __syncthreads();
        bs[t] += v;
        __syncthreads();
    }
    int run = bs[t] - s;
#pragma unroll
    for (int q = 0; q < 32; q++) {
        int i = t * 32 + q;
        d_kptr[i] = run; d_kcur[i] = run;
        run += loc[q];
    }
    if (t == 255) d_kptr[NN] = run;
}
__global__ void k_kfill() {
    int w = blockIdx.x * 256 + threadIdx.x;
    if (w >= NN * KT) return;
    int i = w / KT, j = d_tidx[w];
    float v = d_tval[w];
    int pos = atomicAdd(&d_kcur[i], 1);
    d_kidx[pos] = j; d_kval[pos] = v;
    if (!d_kmut[w]) {
        int pos2 = atomicAdd(&d_kcur[j], 1);
        d_kidx[pos2] = i; d_kval[pos2] = v;
    }
}

// -------- dense [8192,256]@[256,256] fp32 GEMM --------
template <int L>
__global__ void k_sgemm_nn(const float* __restrict__ W) {
    const float* A = (L == 0) ? d_fea : d_h1;
    float* C = (L == 0) ? d_xw : d_hw;
    int bm = blockIdx.y, bn = blockIdx.x;
    __shared__ float As[16][132];
    __shared__ float Bs[16][132];
    int tid = threadIdx.x, tm = tid >> 4, tn = tid & 15;
    float acc[8][8];
#pragma unroll
    for (int u = 0; u < 8; u++)
#pragma unroll
        for (int v = 0; v < 8; v++) acc[u][v] = 0.f;
    int r = tid >> 1, kc = (tid & 1) * 8;
    int kb = tid >> 4, nb = (tid & 15) * 8;
    for (int k0 = 0; k0 < 256; k0 += 16) {
        float4 a0 = *(const float4*)&A[(size_t)(bm*128+r)*256 + k0 + kc];
        float4 a1 = *(const float4*)&A[(size_t)(bm*128+r)*256 + k0 + kc + 4];
        float4 b0 = *(const float4*)&W[(size_t)(k0+kb)*256 + bn*128 + nb];
        float4 b1 = *(const float4*)&W[(size_t)(k0+kb)*256 + bn*128 + nb + 4];
        __syncthreads();
        As[kc+0][r]=a0.x; As[kc+1][r]=a0.y; As[kc+2][r]=a0.z; As[kc+3][r]=a0.w;
        As[kc+4][r]=a1.x; As[kc+5][r]=a1.y; As[kc+6][r]=a1.z; As[kc+7][r]=a1.w;
        *(float4*)&Bs[kb][nb] = b0;
        *(float4*)&Bs[kb][nb+4] = b1;
        __syncthreads();
#pragma unroll
        for (int kk = 0; kk < 16; kk++) {
            float av[8], bv[8];
#pragma unroll
            for (int u = 0; u < 8; u++) { av[u]=As[kk][tm*8+u]; bv[u]=Bs[kk][tn*8+u]; }
#pragma unroll
            for (int u = 0; u < 8; u++)
#pragma unroll
                for (int vv = 0; vv < 8; vv++) acc[u][vv] += av[u]*bv[vv];
        }
    }
#pragma unroll
    for (int u = 0; u < 8; u++) {
        float* crow = &C[(size_t)(bm*128+tm*8+u)*256 + bn*128 + tn*8];
        *(float4*)crow     = make_float4(acc[u][0],acc[u][1],acc[u][2],acc[u][3]);
        *(float4*)(crow+4) = make_float4(acc[u][4],acc[u][5],acc[u][6],acc[u][7]);
    }
}

// -------- gather-based A_tot @ X (one warp per row, no atomics) --------
template <int L>
__global__ void k_spmm_gather(const float* __restrict__ alphap) {
    int gw = (blockIdx.x * 256 + threadIdx.x) >> 5, lane = threadIdx.x & 31;
    if (gw >= NN) return;
    const float* X = (L == 0) ? d_xw : d_hw;
    float* out = (L == 0) ? d_h1 : d_emb;
    float alpha = *alphap;
    float di = d_dinv[gw];
    const float4* xr = (const float4*)(X + (size_t)gw * 256);
    float4 x0 = xr[lane], x1 = xr[lane + 32];
    float sc = di * di;
    float4 a0 = make_float4(sc*x0.x, sc*x0.y, sc*x0.z, sc*x0.w);
    float4 a1 = make_float4(sc*x1.x, sc*x1.y, sc*x1.z, sc*x1.w);
    int b = d_rptr[gw], e = d_rptr[gw + 1];
    for (int p = b; p < e; p++) {
        float wv = d_cw[p];
        const float4* xs = (const float4*)(X + (size_t)d_csrc[p] * 256);
        fma4(a0, wv, xs[lane]); fma4(a1, wv, xs[lane + 32]);
    }
    a0.x*=alpha; a0.y*=alpha; a0.z*=alpha; a0.w*=alpha;
    a1.x*=alpha; a1.y*=alpha; a1.z*=alpha; a1.w*=alpha;
    int kb = d_kptr[gw], ke = d_kptr[gw + 1];
    for (int p = kb; p < ke; p++) {
        float v = d_kval[p];
        const float4* xs = (const float4*)(X + (size_t)d_kidx[p] * 256);
        fma4(a0, v, xs[lane]); fma4(a1, v, xs[lane + 32]);
    }
    if (L == 0) {
        a0.x=fmaxf(a0.x,0.f); a0.y=fmaxf(a0.y,0.f); a0.z=fmaxf(a0.z,0.f); a0.w=fmaxf(a0.w,0.f);
        a1.x=fmaxf(a1.x,0.f); a1.y=fmaxf(a1.y,0.f); a1.z=fmaxf(a1.z,0.f); a1.w=fmaxf(a1.w,0.f);
    }
    float4* orow = (float4*)(out + (size_t)gw * 256);
    orow[lane] = a0; orow[lane + 32] = a1;
}

// -------- classification --------
__global__ void k_cls_scatter(const int* __restrict__ labels, const int* __restrict__ nidx) {
    int w = (blockIdx.x*256+threadIdx.x) >> 5, lane = threadIdx.x & 31;
    if (w >= NSEL) return;
    int lbl = labels[w];
    const float4* er = (const float4*)(d_emb + (size_t)nidx[w]*HIDD);
    float4* sr = (float4*)(d_sums + lbl*HIDD);
#pragma unroll
    for (int q = 0; q < 2; q++) {
        int f = lane + 32*q; float4 v = er[f];
        red4(&sr[f], v.x, v.y, v.z, v.w);
    }
    if (lane == 0) atomicAdd(&d_cnt[lbl], 1.f);
}
__global__ void k_proto() {
    int c = blockIdx.x, t = threadIdx.x;
    float p = d_sums[c*HIDD+t] / fmaxf(d_cnt[c], 1.f);
    __shared__ float red[256];
    red[t] = p*p;
    __syncthreads();
    for (int s = 128; s > 0; s >>= 1) { if (t < s) red[t] += red[t+s]; __syncthreads(); }
    d_pn[c*HIDD+t] = p / (sqrtf(red[0]) + EPSF);
}
__global__ void k_out(const int* __restrict__ nidx, float* __restrict__ out) {
    int w = (blockIdx.x*256+threadIdx.x) >> 5, lane = threadIdx.x & 31;
    if (w >= NSEL) return;
    const float* er = d_emb + (size_t)nidx[w]*HIDD;
    float v[8]; float ss = 0.f;
#pragma unroll
    for (int q = 0; q < 8; q++) { v[q] = er[lane+32*q]; ss += v[q]*v[q]; }
    ss = warp_sum(ss);
    float rn = 1.f / (sqrtf(ss) + EPSF);
#pragma unroll
    for (int c = 0; c < NCLS; c++) {
        float dp = 0.f;
#pragma unroll
        for (int q = 0; q < 8; q++) dp += v[q] * d_pn[c*HIDD + lane + 32*q];
        dp = warp_sum(dp);
        if (lane == 0) out[w*NCLS + c] = dp * rn * 5.0f;
    }
}

extern "C" void kernel_launch(void* const* d_in, const int* in_sizes, int n_in,
                              void* d_out, int out_size) {
    const float* x   = (const float*)d_in[0];
    const float* cw  = (const float*)d_in[1];
    const float* alp = (const float*)d_in[2];
    const float* ps  = (const float*)d_in[3];
    const float* st  = (const float*)d_in[4];
    const float* bal = (const float*)d_in[5];
    const float* W1  = (const float*)d_in[6];
    const float* W2  = (const float*)d_in[7];
    const int*   ei  = (const int*)d_in[8];
    const int*   lab = (const int*)d_in[9];
    const int*   nix = (const int*)d_in[10];
    float* out = (float*)d_out;
    const int* esrc = ei;
    const int* edst = ei + NE;

    cudaFuncSetAttribute(k_mma_sims, cudaFuncAttributeMaxDynamicSharedMemorySize, SIMS_SMEM);

    k_fea<<<NN*FIN/256, 256>>>(x, cw, ps, st);
    k_cnt<<<NE/256, 256>>>(edst);
    k_scan<<<1, 256>>>();
    k_fill<<<NE/256, 256>>>(esrc, edst);
    k_agg_h<<<NN/8, 256>>>(bal);
    k_mma_sims<<<dim3(64, 64), 256, SIMS_SMEM>>>();
    k_topk<<<NN, 256>>>(alp);
    k_kcount<<<NN*KT/8, 256>>>();
    k_kscan<<<1, 256>>>();
    k_kfill<<<(NN*KT+255)/256, 256>>>();

    k_sgemm_nn<0><<<dim3(2, 64), 256>>>(W1);
    k_spmm_gather<0><<<NN/8, 256>>>(alp);
    k_sgemm_nn<1><<<dim3(2, 64), 256>>>(W2);
    k_spmm_gather<1><<<NN/8, 256>>>(alp);

    k_cls_scatter<<<NSEL/8, 256>>>(lab, nix);
    k_proto<<<NCLS, 256>>>();
    k_out<<<NSEL/8, 256>>>(nix, out);
}

// round 6
// speedup vs baseline: 1.8002x; 1.0084x over previous
#include <cuda_runtime.h>
#include <cuda_bf16.h>
#include <math.h>
#include <float.h>
#include <stdint.h>

#define NN   8192
#define FIN  256
#define HIDD 256
#define NE   131072
#define KT   17
#define NCAND 24
#define NCLS 10
#define NSEL 4096
#define EPSF 1e-8f

__device__ __align__(16) float d_fea[NN * FIN];
__device__ float d_dinv[NN];
__device__ int   d_cnt_e[NN];          // self-cleaning (reset in k_scan)
__device__ int   d_rptr[NN + 1];
__device__ int   d_cur[NN];
__device__ int   d_csrc[NE];
__device__ float d_cw[NE];
__device__ __align__(16) float d_hn[NN * 512];
__device__ __align__(16) __nv_bfloat16 d_hb[NN * 512];
__device__ __nv_bfloat16 d_simh[(size_t)NN * NN];   // 128 MB
__device__ int   d_tidx[NN * KT];
__device__ float d_tval[NN * KT];
__device__ int   d_kcnt[NN];           // self-cleaning (reset in k_kscan)
__device__ int   d_kptr[NN + 1];
__device__ int   d_kcur[NN];
__device__ unsigned char d_kmut[NN * KT];
__device__ int   d_kidx[NN * KT * 2];
__device__ float d_kval[NN * KT * 2];
__device__ __align__(16) float d_xw[NN * HIDD];
__device__ __align__(16) float d_h1[NN * HIDD];
__device__ __align__(16) float d_hw[NN * HIDD];
__device__ __align__(16) float d_emb[NN * HIDD];
__device__ __align__(16) float d_sums[NCLS * HIDD]; // self-cleaning (reset in k_proto)
__device__ float d_cnt[NCLS];                       // self-cleaning (reset in k_proto)
__device__ float d_pn[NCLS * HIDD];

__device__ __forceinline__ float warp_sum(float v) {
#pragma unroll
    for (int o = 16; o > 0; o >>= 1) v += __shfl_xor_sync(0xffffffffu, v, o);
    return v;
}
__device__ __forceinline__ void red4(float4* addr, float a, float b, float c, float d) {
    asm volatile("red.global.add.v4.f32 [%0], {%1,%2,%3,%4};"
                 :: "l"(addr), "f"(a), "f"(b), "f"(c), "f"(d) : "memory");
}
__device__ __forceinline__ void fma4(float4& a, float w, const float4 v) {
    a.x += w * v.x; a.y += w * v.y; a.z += w * v.z; a.w += w * v.w;
}
__device__ __forceinline__ uint2 pack_bf16x4(float4 v) {
    __nv_bfloat162 lo = __floats2bfloat162_rn(v.x, v.y);
    __nv_bfloat162 hi = __floats2bfloat162_rn(v.z, v.w);
    uint2 r;
    r.x = *reinterpret_cast<uint32_t*>(&lo);
    r.y = *reinterpret_cast<uint32_t*>(&hi);
    return r;
}

// -------- stage 1: fea = elu(...)  (+ fused degree count) --------
__global__ void k_fea(const float* __restrict__ x, const float* __restrict__ cw,
                      const float* __restrict__ ps, const float* __restrict__ st,
                      const int* __restrict__ dst) {
    int idx = blockIdx.x * 256 + threadIdx.x;
    int f = idx & (FIN - 1);
    float z = x[idx] * (cw[0] * ps[f] + cw[1] * st[f]);
    d_fea[idx] = z > 0.f ? z : expm1f(z);
    if (idx < NE) atomicAdd(&d_cnt_e[dst[idx]], 1);
}
// -------- CSR build: scan (+reset) -> fill --------
__global__ void k_scan() {                 // 1 block, 256 threads, 32 rows each
    __shared__ int bs[256];
    int t = threadIdx.x;
    int loc[32]; int s = 0;
#pragma unroll
    for (int q = 0; q < 32; q++) {
        loc[q] = d_cnt_e[t * 32 + q];
        d_cnt_e[t * 32 + q] = 0;           // self-clean for next replay
        s += loc[q];
    }
    bs[t] = s; __syncthreads();
    for (int off = 1; off < 256; off <<= 1) {
        int v = (t >= off) ? bs[t - off] : 0;
        __syncthreads();
        bs[t] += v;
        __syncthreads();
    }
    int run = bs[t] - s;
#pragma unroll
    for (int q = 0; q < 32; q++) {
        int i = t * 32 + q;
        d_rptr[i] = run; d_cur[i] = run;
        d_dinv[i] = rsqrtf((float)(loc[q] + 1));
        run += loc[q];
    }
    if (t == 255) d_rptr[NN] = run;
}
__global__ void k_fill(const int* __restrict__ src, const int* __restrict__ dst) {
    int e = blockIdx.x * 256 + threadIdx.x;
    if (e >= NE) return;
    int s = src[e], d = dst[e];
    int pos = atomicAdd(&d_cur[d], 1);
    d_csrc[pos] = s;
    d_cw[pos] = d_dinv[s] * d_dinv[d];
}
// -------- fused aggregate-gather + h-normalize + bf16 --------
__global__ void k_agg_h(const float* __restrict__ bal) {
    int gw = (blockIdx.x * 256 + threadIdx.x) >> 5, lane = threadIdx.x & 31;
    if (gw >= NN) return;
    float di = d_dinv[gw];
    const float4* fr = (const float4*)(d_fea + (size_t)gw * 256);
    float4 f0 = fr[lane], f1 = fr[lane + 32];
    float sc = di * di;
    float4 a0 = make_float4(sc*f0.x, sc*f0.y, sc*f0.z, sc*f0.w);
    float4 a1 = make_float4(sc*f1.x, sc*f1.y, sc*f1.z, sc*f1.w);
    int b = d_rptr[gw], e = d_rptr[gw + 1];
    int p = b;
    for (; p + 1 < e; p += 2) {
        float w0 = d_cw[p], w1 = d_cw[p + 1];
        const float4* s0 = (const float4*)(d_fea + (size_t)d_csrc[p] * 256);
        const float4* s1 = (const float4*)(d_fea + (size_t)d_csrc[p + 1] * 256);
        float4 v00 = s0[lane], v01 = s0[lane + 32];
        float4 v10 = s1[lane], v11 = s1[lane + 32];
        fma4(a0, w0, v00); fma4(a1, w0, v01);
        fma4(a0, w1, v10); fma4(a1, w1, v11);
    }
    if (p < e) {
        float wv = d_cw[p];
        const float4* fs = (const float4*)(d_fea + (size_t)d_csrc[p] * 256);
        fma4(a0, wv, fs[lane]); fma4(a1, wv, fs[lane + 32]);
    }
    const float4* bb = (const float4*)bal;
    float4 bA = bb[lane], bB = bb[lane + 32], bC = bb[64 + lane], bD = bb[96 + lane];
    float4 hA = make_float4(f0.x*bA.x, f0.y*bA.y, f0.z*bA.z, f0.w*bA.w);
    float4 hB = make_float4(f1.x*bB.x, f1.y*bB.y, f1.z*bB.z, f1.w*bB.w);
    float4 hC = make_float4(a0.x*bC.x, a0.y*bC.y, a0.z*bC.z, a0.w*bC.w);
    float4 hD = make_float4(a1.x*bD.x, a1.y*bD.y, a1.z*bD.z, a1.w*bD.w);
    float ss = hA.x*hA.x+hA.y*hA.y+hA.z*hA.z+hA.w*hA.w
             + hB.x*hB.x+hB.y*hB.y+hB.z*hB.z+hB.w*hB.w
             + hC.x*hC.x+hC.y*hC.y+hC.z*hC.z+hC.w*hC.w
             + hD.x*hD.x+hD.y*hD.y+hD.z*hD.z+hD.w*hD.w;
    ss = warp_sum(ss);
    float rn = 1.f / (sqrtf(ss) + EPSF);
    hA.x*=rn; hA.y*=rn; hA.z*=rn; hA.w*=rn;
    hB.x*=rn; hB.y*=rn; hB.z*=rn; hB.w*=rn;
    hC.x*=rn; hC.y*=rn; hC.z*=rn; hC.w*=rn;
    hD.x*=rn; hD.y*=rn; hD.z*=rn; hD.w*=rn;
    float4* hr = (float4*)(d_hn + (size_t)gw * 512);
    hr[lane] = hA; hr[lane + 32] = hB; hr[64 + lane] = hC; hr[96 + lane] = hD;
    uint2* hb = (uint2*)(d_hb + (size_t)gw * 512);
    hb[lane] = pack_bf16x4(hA); hb[lane + 32] = pack_bf16x4(hB);
    hb[64 + lane] = pack_bf16x4(hC); hb[96 + lane] = pack_bf16x4(hD);
}

// ======== sims = hb @ hb^T via mma.sync, bf16 output ========
__device__ __forceinline__ uint32_t smem_u32(const void* p) {
    uint32_t a;
    asm("{ .reg .u64 t; cvta.to.shared.u64 t, %1; cvt.u32.u64 %0, t; }" : "=r"(a) : "l"(p));
    return a;
}
__device__ __forceinline__ void ldsm4(uint32_t* r, uint32_t addr) {
    asm volatile("ldmatrix.sync.aligned.m8n8.x4.shared.b16 {%0,%1,%2,%3}, [%4];"
                 : "=r"(r[0]), "=r"(r[1]), "=r"(r[2]), "=r"(r[3]) : "r"(addr));
}
__device__ __forceinline__ void mma16816(float* c, const uint32_t* a, uint32_t b0, uint32_t b1) {
    asm volatile("mma.sync.aligned.m16n8k16.row.col.f32.bf16.bf16.f32 "
                 "{%0,%1,%2,%3}, {%4,%5,%6,%7}, {%8,%9}, {%0,%1,%2,%3};"
                 : "+f"(c[0]), "+f"(c[1]), "+f"(c[2]), "+f"(c[3])
                 : "r"(a[0]), "r"(a[1]), "r"(a[2]), "r"(a[3]), "r"(b0), "r"(b1));
}
__device__ __forceinline__ void sims_load(uint32_t sbase, const __nv_bfloat16* Ag,
                                          const __nv_bfloat16* Bg, int c, int tid) {
#pragma unroll
    for (int h = 0; h < 2; h++) {
        const __nv_bfloat16* G = h ? Bg : Ag;
        uint32_t base = sbase + (uint32_t)h * 16384;
#pragma unroll
        for (int q = 0; q < 4; q++) {
            int seg = tid + 256 * q;
            int r = seg >> 3, s8 = seg & 7;
            uint32_t dst = base + r * 128 + ((s8 ^ (r & 7)) << 4);
            const char* src = (const char*)(G + (size_t)r * 512 + c * 64 + s8 * 8);
            asm volatile("cp.async.cg.shared.global [%0], [%1], 16;"
                         :: "r"(dst), "l"(src) : "memory");
        }
    }
    asm volatile("cp.async.commit_group;" ::: "memory");
}
#define SIMS_SMEM 66048

__global__ void __launch_bounds__(256, 2) k_mma_sims() {
    int bi = blockIdx.y, bj = blockIdx.x;
    if (bj < bi) return;
    extern __shared__ char smem[];
    uint32_t sb = smem_u32(smem);
    int tid = threadIdx.x;
    int lane = tid & 31, w = tid >> 5;
    int wm = (w & 1) * 64, wn = (w >> 1) * 32;

    const __nv_bfloat16* Ag = d_hb + (size_t)bi * 128 * 512;
    const __nv_bfloat16* Bg = d_hb + (size_t)bj * 128 * 512;

    float acc[4][4][4];
#pragma unroll
    for (int mt = 0; mt < 4; mt++)
#pragma unroll
        for (int nt = 0; nt < 4; nt++)
#pragma unroll
            for (int e = 0; e < 4; e++) acc[mt][nt][e] = 0.f;

    sims_load(sb, Ag, Bg, 0, tid);
    int lr = lane & 15, lks = lane >> 4;
    for (int c = 0; c < 8; c++) {
        if (c < 7) sims_load(sb + ((c + 1) & 1) * 32768, Ag, Bg, c + 1, tid);
        if (c < 7) asm volatile("cp.async.wait_group 1;" ::: "memory");
        else       asm volatile("cp.async.wait_group 0;" ::: "memory");
        __syncthreads();
        uint32_t aB = sb + (c & 1) * 32768, bB = aB + 16384;
#pragma unroll
        for (int ks = 0; ks < 4; ks++) {
            int segk = ks * 2 + lks;
            uint32_t a[4][4], b[2][4];
#pragma unroll
            for (int mt = 0; mt < 4; mt++) {
                int r = wm + mt * 16 + lr;
                ldsm4(a[mt], aB + r * 128 + ((segk ^ (r & 7)) << 4));
            }
#pragma unroll
            for (int bt = 0; bt < 2; bt++) {
                int r = wn + bt * 16 + lr;
                ldsm4(b[bt], bB + r * 128 + ((segk ^ (r & 7)) << 4));
            }
#pragma unroll
            for (int mt = 0; mt < 4; mt++)
#pragma unroll
                for (int nt = 0; nt < 4; nt++)
                    mma16816(acc[mt][nt], a[mt], b[nt >> 1][nt & 1], b[nt >> 1][(nt & 1) + 2]);
        }
        __syncthreads();
    }
    float* sf = (float*)smem;
    int g = lane >> 2, tq = lane & 3;
#pragma unroll
    for (int mt = 0; mt < 4; mt++)
#pragma unroll
        for (int nt = 0; nt < 4; nt++) {
            int r0 = wm + mt * 16 + g, c0 = wn + nt * 8 + tq * 2;
            sf[r0 * 129 + c0]           = acc[mt][nt][0];
            sf[r0 * 129 + c0 + 1]       = acc[mt][nt][1];
            sf[(r0 + 8) * 129 + c0]     = acc[mt][nt][2];
            sf[(r0 + 8) * 129 + c0 + 1] = acc[mt][nt][3];
        }
    __syncthreads();
    size_t gi0 = (size_t)bi * 128, gj0 = (size_t)bj * 128;
    if (bi != bj) {
        // full tiles, packed bf16x2 stores
        for (int it = tid; it < 128 * 64; it += 256) {            // direct
            int r = it >> 6, c2 = (it & 63) * 2;
            __nv_bfloat162 p = __floats2bfloat162_rn(sf[r * 129 + c2], sf[r * 129 + c2 + 1]);
            *(__nv_bfloat162*)&d_simh[(gi0 + r) * NN + gj0 + c2] = p;
        }
        for (int it = tid; it < 128 * 64; it += 256) {            // mirror
            int j = it >> 6, i2 = (it & 63) * 2;
            __nv_bfloat162 p = __floats2bfloat162_rn(sf[i2 * 129 + j], sf[(i2 + 1) * 129 + j]);
            *(__nv_bfloat162*)&d_simh[(gj0 + j) * NN + gi0 + i2] = p;
        }
    } else {
        // diagonal tile: single writer for the whole block, symmetric by construction
        for (int it = tid; it < 128 * 64; it += 256) {
            int r = it >> 6, c2 = (it & 63) * 2;
            float v0 = (c2 >= r)     ? sf[r * 129 + c2]     : sf[c2 * 129 + r];
            float v1 = (c2 + 1 >= r) ? sf[r * 129 + c2 + 1] : sf[(c2 + 1) * 129 + r];
            __nv_bfloat162 p = __floats2bfloat162_rn(v0, v1);
            *(__nv_bfloat162*)&d_simh[(gi0 + r) * NN + gj0 + c2] = p;
        }
    }
}

// -------- top-24 approx (bf16 sims) + exact fp32 rescore -> top-17 --------
__global__ void k_topk(const float* __restrict__ alphap) {
    int row = blockIdx.x, t = threadIdx.x;
    const __nv_bfloat16* srow = d_simh + (size_t)row * NN;
    float v[32];
#pragma unroll
    for (int q = 0; q < 32; q++) v[q] = __bfloat162float(srow[q * 256 + t]);
    unsigned rem = 0;
    float m = -FLT_MAX; int a = 0;
#pragma unroll
    for (int q = 0; q < 32; q++) if (v[q] > m) { m = v[q]; a = q; }
    __shared__ float wv[8];
    __shared__ int   wi[8];
    __shared__ int   cand[NCAND];
    __shared__ float cex[NCAND];
    for (int it = 0; it < NCAND; it++) {
        float mv = m; int mi = a * 256 + t;
#pragma unroll
        for (int o = 16; o > 0; o >>= 1) {
            float ov = __shfl_xor_sync(0xffffffffu, mv, o);
            int   oi = __shfl_xor_sync(0xffffffffu, mi, o);
            if (ov > mv || (ov == mv && oi < mi)) { mv = ov; mi = oi; }
        }
        if ((t & 31) == 0) { wv[t >> 5] = mv; wi[t >> 5] = mi; }
        __syncthreads();
        if (t == 0) {
            float bv = wv[0]; int bx = wi[0];
#pragma unroll
            for (int k = 1; k < 8; k++)
                if (wv[k] > bv || (wv[k] == bv && wi[k] < bx)) { bv = wv[k]; bx = wi[k]; }
            cand[it] = bx;
        }
        __syncthreads();
        int bx = cand[it];
        if ((bx & 255) == t) {
            rem |= 1u << (bx >> 8);
            m = -FLT_MAX; a = 0;
#pragma unroll
            for (int q = 0; q < 32; q++) {
                float vq = ((rem >> q) & 1u) ? -FLT_MAX : v[q];
                if (vq > m) { m = vq; a = q; }
            }
        }
    }
    int w = t >> 5, lane = t & 31;
    const float* hr = d_hn + (size_t)row * 512;
#pragma unroll
    for (int c = w * 3; c < w * 3 + 3; c++) {
        const float* hj = d_hn + (size_t)cand[c] * 512;
        float s = 0.f;
        for (int e = lane; e < 512; e += 32) s += hr[e] * hj[e];
        s = warp_sum(s);
        if (lane == 0) cex[c] = s;
    }
    __syncthreads();
    if (t == 0) {
        float onema = 1.f - *alphap;
        unsigned used = 0;
        for (int it = 0; it < KT; it++) {
            float bv = -FLT_MAX; int bc = -1;
            for (int c = 0; c < NCAND; c++) {
                if ((used >> c) & 1u) continue;
                if (bc < 0 || cex[c] > bv || (cex[c] == bv && cand[c] < cand[bc]))
                    { bv = cex[c]; bc = c; }
            }
            used |= 1u << bc;
            d_tidx[row * KT + it] = cand[bc];
            d_tval[row * KT + it] = onema * fmaxf(bv, 0.f);
        }
    }
}

// -------- kNN symmetric CSR build --------
__global__ void k_kcount() {
    int w = (blockIdx.x * 256 + threadIdx.x) >> 5, lane = threadIdx.x & 31;
    if (w >= NN * KT) return;
    int i = w / KT, j = d_tidx[w];
    int cand = (lane < KT) ? d_tidx[j * KT + lane] : -1;
    unsigned f = __ballot_sync(0xffffffffu, cand == i);
    if (lane == 0) {
        atomicAdd(&d_kcnt[i], 1);
        d_kmut[w] = (f != 0);
        if (!f) atomicAdd(&d_kcnt[j], 1);
    }
}
__global__ void k_kscan() {
    __shared__ int bs[256];
    int t = threadIdx.x;
    int loc[32]; int s = 0;
#pragma unroll
    for (int q = 0; q < 32; q++) {
        loc[q] = d_kcnt[t * 32 + q];
        d_kcnt[t * 32 + q] = 0;            // self-clean
        s += loc[q];
    }
    bs[t] = s; __syncthreads();
    for (int off = 1; off < 256; off <<= 1) {
        int v = (t >= off) ? bs[t - off] : 0;
        __syncthreads();
        bs[t] += v;
        __syncthreads();
    }
    int run = bs[t] - s;
#pragma unroll
    for (int q = 0; q < 32; q++) {
        int i = t * 32 + q;
        d_kptr[i] = run; d_kcur[i] = run;
        run += loc[q];
    }
    if (t == 255) d_kptr[NN] = run;
}
__global__ void k_kfill() {
    int w = blockIdx.x * 256 + threadIdx.x;
    if (w >= NN * KT) return;
    int i = w / KT, j = d_tidx[w];
    float v = d_tval[w];
    int pos = atomicAdd(&d_kcur[i], 1);
    d_kidx[pos] = j; d_kval[pos] = v;
    if (!d_kmut[w]) {
        int pos2 = atomicAdd(&d_kcur[j], 1);
        d_kidx[pos2] = i; d_kval[pos2] = v;
    }
}

// -------- dense [8192,256]@[256,256] fp32 GEMM --------
template <int L>
__global__ void k_sgemm_nn(const float* __restrict__ W) {
    const float* A = (L == 0) ? d_fea : d_h1;
    float* C = (L == 0) ? d_xw : d_hw;
    int bm = blockIdx.y, bn = blockIdx.x;
    __shared__ float As[16][132];
    __shared__ float Bs[16][132];
    int tid = threadIdx.x, tm = tid >> 4, tn = tid & 15;
    float acc[8][8];
#pragma unroll
    for (int u = 0; u < 8; u++)
#pragma unroll
        for (int v = 0; v < 8; v++) acc[u][v] = 0.f;
    int r = tid >> 1, kc = (tid & 1) * 8;
    int kb = tid >> 4, nb = (tid & 15) * 8;
    for (int k0 = 0; k0 < 256; k0 += 16) {
        float4 a0 = *(const float4*)&A[(size_t)(bm*128+r)*256 + k0 + kc];
        float4 a1 = *(const float4*)&A[(size_t)(bm*128+r)*256 + k0 + kc + 4];
        float4 b0 = *(const float4*)&W[(size_t)(k0+kb)*256 + bn*128 + nb];
        float4 b1 = *(const float4*)&W[(size_t)(k0+kb)*256 + bn*128 + nb + 4];
        __syncthreads();
        As[kc+0][r]=a0.x; As[kc+1][r]=a0.y; As[kc+2][r]=a0.z; As[kc+3][r]=a0.w;
        As[kc+4][r]=a1.x; As[kc+5][r]=a1.y; As[kc+6][r]=a1.z; As[kc+7][r]=a1.w;
        *(float4*)&Bs[kb][nb] = b0;
        *(float4*)&Bs[kb][nb+4] = b1;
        __syncthreads();
#pragma unroll
        for (int kk = 0; kk < 16; kk++) {
            float av[8], bv[8];
#pragma unroll
            for (int u = 0; u < 8; u++) { av[u]=As[kk][tm*8+u]; bv[u]=Bs[kk][tn*8+u]; }
#pragma unroll
            for (int u = 0; u < 8; u++)
#pragma unroll
                for (int vv = 0; vv < 8; vv++) acc[u][vv] += av[u]*bv[vv];
        }
    }
#pragma unroll
    for (int u = 0; u < 8; u++) {
        float* crow = &C[(size_t)(bm*128+tm*8+u)*256 + bn*128 + tn*8];
        *(float4*)crow     = make_float4(acc[u][0],acc[u][1],acc[u][2],acc[u][3]);
        *(float4*)(crow+4) = make_float4(acc[u][4],acc[u][5],acc[u][6],acc[u][7]);
    }
}

// -------- gather-based A_tot @ X (one warp per row, no atomics) --------
template <int L>
__global__ void k_spmm_gather(const float* __restrict__ alphap) {
    int gw = (blockIdx.x * 256 + threadIdx.x) >> 5, lane = threadIdx.x & 31;
    if (gw >= NN) return;
    const float* X = (L == 0) ? d_xw : d_hw;
    float* out = (L == 0) ? d_h1 : d_emb;
    float alpha = *alphap;
    float di = d_dinv[gw];
    const float4* xr = (const float4*)(X + (size_t)gw * 256);
    float4 x0 = xr[lane], x1 = xr[lane + 32];
    float sc = di * di;
    float4 a0 = make_float4(sc*x0.x, sc*x0.y, sc*x0.z, sc*x0.w);
    float4 a1 = make_float4(sc*x1.x, sc*x1.y, sc*x1.z, sc*x1.w);
    int b = d_rptr[gw], e = d_rptr[gw + 1];
    int p = b;
    for (; p + 1 < e; p += 2) {
        float w0 = d_cw[p], w1 = d_cw[p + 1];
        const float4* s0 = (const float4*)(X + (size_t)d_csrc[p] * 256);
        const float4* s1 = (const float4*)(X + (size_t)d_csrc[p + 1] * 256);
        float4 v00 = s0[lane], v01 = s0[lane + 32];
        float4 v10 = s1[lane], v11 = s1[lane + 32];
        fma4(a0, w0, v00); fma4(a1, w0, v01);
        fma4(a0, w1, v10); fma4(a1, w1, v11);
    }
    if (p < e) {
        float wv = d_cw[p];
        const float4* xs = (const float4*)(X + (size_t)d_csrc[p] * 256);
        fma4(a0, wv, xs[lane]); fma4(a1, wv, xs[lane + 32]);
    }
    a0.x*=alpha; a0.y*=alpha; a0.z*=alpha; a0.w*=alpha;
    a1.x*=alpha; a1.y*=alpha; a1.z*=alpha; a1.w*=alpha;
    int kb = d_kptr[gw], ke = d_kptr[gw + 1];
    p = kb;
    for (; p + 1 < ke; p += 2) {
        float w0 = d_kval[p], w1 = d_kval[p + 1];
        const float4* s0 = (const float4*)(X + (size_t)d_kidx[p] * 256);
        const float4* s1 = (const float4*)(X + (size_t)d_kidx[p + 1] * 256);
        float4 v00 = s0[lane], v01 = s0[lane + 32];
        float4 v10 = s1[lane], v11 = s1[lane + 32];
        fma4(a0, w0, v00); fma4(a1, w0, v01);
        fma4(a0, w1, v10); fma4(a1, w1, v11);
    }
    if (p < ke) {
        float v = d_kval[p];
        const float4* xs = (const float4*)(X + (size_t)d_kidx[p] * 256);
        fma4(a0, v, xs[lane]); fma4(a1, v, xs[lane + 32]);
    }
    if (L == 0) {
        a0.x=fmaxf(a0.x,0.f); a0.y=fmaxf(a0.y,0.f); a0.z=fmaxf(a0.z,0.f); a0.w=fmaxf(a0.w,0.f);
        a1.x=fmaxf(a1.x,0.f); a1.y=fmaxf(a1.y,0.f); a1.z=fmaxf(a1.z,0.f); a1.w=fmaxf(a1.w,0.f);
    }
    float4* orow = (float4*)(out + (size_t)gw * 256);
    orow[lane] = a0; orow[lane + 32] = a1;
}

// -------- classification --------
__global__ void k_cls_scatter(const int* __restrict__ labels, const int* __restrict__ nidx) {
    int w = (blockIdx.x*256+threadIdx.x) >> 5, lane = threadIdx.x & 31;
    if (w >= NSEL) return;
    int lbl = labels[w];
    const float4* er = (const float4*)(d_emb + (size_t)nidx[w]*HIDD);
    float4* sr = (float4*)(d_sums + lbl*HIDD);
#pragma unroll
    for (int q = 0; q < 2; q++) {
        int f = lane + 32*q; float4 v = er[f];
        red4(&sr[f], v.x, v.y, v.z, v.w);
    }
    if (lane == 0) atomicAdd(&d_cnt[lbl], 1.f);
}
__global__ void k_proto() {
    int c = blockIdx.x, t = threadIdx.x;
    float cnt = d_cnt[c];
    float sm = d_sums[c*HIDD+t];
    float p = sm / fmaxf(cnt, 1.f);
    __shared__ float red[256];
    red[t] = p*p;
    __syncthreads();
    for (int s = 128; s > 0; s >>= 1) { if (t < s) red[t] += red[t+s]; __syncthreads(); }
    d_pn[c*HIDD+t] = p / (sqrtf(red[0]) + EPSF);
    d_sums[c*HIDD+t] = 0.f;                // self-clean for next replay
    if (t == 0) d_cnt[c] = 0.f;
}
__global__ void k_out(const int* __restrict__ nidx, float* __restrict__ out) {
    int w = (blockIdx.x*256+threadIdx.x) >> 5, lane = threadIdx.x & 31;
    if (w >= NSEL) return;
    const float* er = d_emb + (size_t)nidx[w]*HIDD;
    float v[8]; float ss = 0.f;
#pragma unroll
    for (int q = 0; q < 8; q++) { v[q] = er[lane+32*q]; ss += v[q]*v[q]; }
    ss = warp_sum(ss);
    float rn = 1.f / (sqrtf(ss) + EPSF);
#pragma unroll
    for (int c = 0; c < NCLS; c++) {
        float dp = 0.f;
#pragma unroll
        for (int q = 0; q < 8; q++) dp += v[q] * d_pn[c*HIDD + lane + 32*q];
        dp = warp_sum(dp);
        if (lane == 0) out[w*NCLS + c] = dp * rn * 5.0f;
    }
}

extern "C" void kernel_launch(void* const* d_in, const int* in_sizes, int n_in,
                              void* d_out, int out_size) {
    const float* x   = (const float*)d_in[0];
    const float* cw  = (const float*)d_in[1];
    const float* alp = (const float*)d_in[2];
    const float* ps  = (const float*)d_in[3];
    const float* st  = (const float*)d_in[4];
    const float* bal = (const float*)d_in[5];
    const float* W1  = (const float*)d_in[6];
    const float* W2  = (const float*)d_in[7];
    const int*   ei  = (const int*)d_in[8];
    const int*   lab = (const int*)d_in[9];
    const int*   nix = (const int*)d_in[10];
    float* out = (float*)d_out;
    const int* esrc = ei;
    const int* edst = ei + NE;

    cudaFuncSetAttribute(k_mma_sims, cudaFuncAttributeMaxDynamicSharedMemorySize, SIMS_SMEM);

    k_fea<<<NN*FIN/256, 256>>>(x, cw, ps, st, edst);
    k_scan<<<1, 256>>>();
    k_fill<<<NE/256, 256>>>(esrc, edst);
    k_agg_h<<<NN/8, 256>>>(bal);
    k_mma_sims<<<dim3(64, 64), 256, SIMS_SMEM>>>();
    k_topk<<<NN, 256>>>(alp);
    k_kcount<<<NN*KT/8, 256>>>();
    k_kscan<<<1, 256>>>();
    k_kfill<<<(NN*KT+255)/256, 256>>>();

    k_sgemm_nn<0><<<dim3(2, 64), 256>>>(W1);
    k_spmm_gather<0><<<NN/8, 256>>>(alp);
    k_sgemm_nn<1><<<dim3(2, 64), 256>>>(W2);
    k_spmm_gather<1><<<NN/8, 256>>>(alp);

    k_cls_scatter<<<NSEL/8, 256>>>(lab, nix);
    k_proto<<<NCLS, 256>>>();
    k_out<<<NSEL/8, 256>>>(nix, out);
}